// round 3
// baseline (speedup 1.0000x reference)
#include <cuda_runtime.h>

// ---------------- problem constants ----------------
#define T_DIM 4
#define B_DIM 16
#define C_DIM 128
#define E_DIM 256
#define H_DIM 32
#define W_DIM 32
#define HW_DIM (H_DIM * W_DIM)
#define TB_DIM (T_DIM * B_DIM)
#define BN_EPS 1e-5f
#define LIF_TAU 0.5f

// ---------------- device scratch (no allocations allowed) ----------------
__device__ float g_spk[(size_t)T_DIM * B_DIM * E_DIM * HW_DIM];  // spikes (67 MB)
__device__ float g_mem[(size_t)T_DIM * B_DIM * E_DIM * HW_DIM];  // pre-LIF (67 MB)
__device__ float g_w3f[E_DIM * C_DIM * 9];
__device__ float g_w4f[E_DIM * E_DIM * 9];
__device__ float g_wrf[E_DIM * C_DIM];
__device__ float g_bias[3 * E_DIM];   // [0]=conv3, [1]=conv4, [2]=residual

// ---------------- f32x2 packed-FMA helpers (sm_100+) ----------------
union F2U { float2 f2; unsigned long long u; };

__device__ __forceinline__ float2 fma2(float2 a, float2 b, float2 c) {
    F2U A, B, C, D;
    A.f2 = a; B.f2 = b; C.f2 = c;
    asm("fma.rn.f32x2 %0, %1, %2, %3;" : "=l"(D.u) : "l"(A.u), "l"(B.u), "l"(C.u));
    return D.f2;
}

__device__ __forceinline__ float2 lds2(const float* p) {
    return *reinterpret_cast<const float2*>(p);
}

// ---------------- BN folding (merged into 2 launches) ----------------
#define W3_N (E_DIM * C_DIM * 9)
#define W4_N (E_DIM * E_DIM * 9)
#define WR_N (E_DIM * C_DIM)

__global__ void fold_all_w(const float* __restrict__ w3, const float* __restrict__ g3, const float* __restrict__ v3,
                           const float* __restrict__ w4, const float* __restrict__ g4, const float* __restrict__ v4,
                           const float* __restrict__ wr, const float* __restrict__ gr, const float* __restrict__ vr,
                           float* __restrict__ w3f, float* __restrict__ w4f, float* __restrict__ wrf) {
    int i = blockIdx.x * blockDim.x + threadIdx.x;
    if (i < W3_N) {
        int e = i / (C_DIM * 9);
        w3f[i] = w3[i] * (g3[e] * rsqrtf(v3[e] + BN_EPS));
    } else if (i < W3_N + W4_N) {
        int j = i - W3_N;
        int e = j / (E_DIM * 9);
        w4f[j] = w4[j] * (g4[e] * rsqrtf(v4[e] + BN_EPS));
    } else if (i < W3_N + W4_N + WR_N) {
        int j = i - W3_N - W4_N;
        int e = j / C_DIM;
        wrf[j] = wr[j] * (gr[e] * rsqrtf(vr[e] + BN_EPS));
    }
}

__global__ void fold_all_b(const float* __restrict__ g3, const float* __restrict__ b3,
                           const float* __restrict__ m3, const float* __restrict__ v3,
                           const float* __restrict__ g4, const float* __restrict__ b4,
                           const float* __restrict__ m4, const float* __restrict__ v4,
                           const float* __restrict__ gr, const float* __restrict__ br,
                           const float* __restrict__ mr, const float* __restrict__ vr,
                           float* __restrict__ bf) {
    int e = threadIdx.x;
    if (e >= E_DIM) return;
    if (blockIdx.x == 0)      bf[e]             = b3[e] - m3[e] * (g3[e] * rsqrtf(v3[e] + BN_EPS));
    else if (blockIdx.x == 1) bf[E_DIM + e]     = b4[e] - m4[e] * (g4[e] * rsqrtf(v4[e] + BN_EPS));
    else                      bf[2 * E_DIM + e] = br[e] - mr[e] * (gr[e] * rsqrtf(vr[e] + BN_EPS));
}

// ---------------- LIF: sequential over T, hard reset (float4) ----------------
__global__ void lif_kernel(const float4* __restrict__ in,
                           float4* __restrict__ out, int npt4) {
    int i = blockIdx.x * blockDim.x + threadIdx.x;
    if (i >= npt4) return;
    float m0 = 0.f, m1 = 0.f, m2 = 0.f, m3 = 0.f;
#pragma unroll
    for (int t = 0; t < T_DIM; ++t) {
        float4 v = in[(size_t)t * npt4 + i];
        m0 = m0 * LIF_TAU + v.x;
        m1 = m1 * LIF_TAU + v.y;
        m2 = m2 * LIF_TAU + v.z;
        m3 = m3 * LIF_TAU + v.w;
        float4 s;
        s.x = (m0 >= 1.0f) ? 1.0f : 0.0f;  if (m0 >= 1.0f) m0 = 0.0f;
        s.y = (m1 >= 1.0f) ? 1.0f : 0.0f;  if (m1 >= 1.0f) m1 = 0.0f;
        s.z = (m2 >= 1.0f) ? 1.0f : 0.0f;  if (m2 >= 1.0f) m2 = 0.0f;
        s.w = (m3 >= 1.0f) ? 1.0f : 0.0f;  if (m3 >= 1.0f) m3 = 0.0f;
        out[(size_t)t * npt4 + i] = s;
    }
}

// ---------------- direct conv (+folded BN, optional residual add) ----------------
// Block: one image n, 32 output channels, 8 rows x 32 cols of pixels. 256 threads.
// Thread: 4 out-channels x 8 pixels (4 f32x2 pairs) -> 16 float2 accumulators.
template <int CIN, int KS, int CC, bool ADD>
__global__ void __launch_bounds__(256, 2)
conv_kernel(const float* __restrict__ in,
            const float* __restrict__ wf,
            const float* __restrict__ bias,
            const float* __restrict__ addend,
            float* __restrict__ out) {
    constexpr int EE      = 4;                  // out-channels per thread
    constexpr int E_BLK   = 8 * EE;             // 32 out-channels per block
    constexpr int ROWS    = 8;
    constexpr int IN_ROWS = ROWS + KS - 1;
    constexpr int IN_COLS = 34;
    constexpr int KK      = KS * KS;
    constexpr int IN_ELEMS = CC * IN_ROWS * IN_COLS;
    constexpr int W_ELEMS  = E_BLK * CC * KK;   // float2 count

    __shared__ __align__(16) float  s_in[IN_ELEMS];
    __shared__ __align__(16) float2 s_w[W_ELEMS];   // weights duplicated {w, w}

    const int n  = blockIdx.z;
    const int eo = blockIdx.y * E_BLK;
    const int r0 = blockIdx.x * ROWS;

    const int tid = threadIdx.x;
    const int wrp = tid >> 5;          // warp id: 4 e-values per warp (broadcast weights)
    const int pg  = tid & 31;
    const int rr  = pg >> 2;           // row within tile: 0..7
    const int x0  = (pg & 3) << 3;     // col base: 0,8,16,24

    float2 acc[EE][4];
#pragma unroll
    for (int i = 0; i < EE; ++i)
#pragma unroll
        for (int j = 0; j < 4; ++j) acc[i][j] = make_float2(0.0f, 0.0f);

    for (int c0 = 0; c0 < CIN; c0 += CC) {
        __syncthreads();
        // ---- stage input tile (halo + zero pad for KS==3) ----
        const float* inb = in + ((size_t)n * CIN + c0) * HW_DIM;
        for (int idx = tid; idx < IN_ELEMS; idx += 256) {
            int c   = idx / (IN_ROWS * IN_COLS);
            int rem = idx - c * (IN_ROWS * IN_COLS);
            int iy  = rem / IN_COLS;
            int ix  = rem - iy * IN_COLS;
            float val = 0.0f;
            if (KS == 3) {
                int gy = r0 + iy - 1;
                int gx = ix - 1;
                if ((unsigned)gy < (unsigned)H_DIM && (unsigned)gx < (unsigned)W_DIM)
                    val = inb[c * HW_DIM + gy * W_DIM + gx];
            } else {
                if (ix < W_DIM)
                    val = inb[c * HW_DIM + (r0 + iy) * W_DIM + ix];
            }
            s_in[idx] = val;
        }
        // ---- stage weights, duplicated into both f32x2 lanes ----
        for (int idx = tid; idx < W_ELEMS; idx += 256) {
            int e   = idx / (CC * KK);
            int rem = idx - e * (CC * KK);
            int c   = rem / KK;
            int k   = rem - c * KK;
            float wv = wf[((size_t)(eo + e) * CIN + (c0 + c)) * KK + k];
            s_w[idx] = make_float2(wv, wv);
        }
        __syncthreads();

        if (KS == 3) {
            for (int c = 0; c < CC; ++c) {
#pragma unroll
                for (int ky = 0; ky < 3; ++ky) {
                    const float* rowp = &s_in[(c * IN_ROWS + rr + ky) * IN_COLS + x0];
                    float2 q0 = lds2(rowp + 0);
                    float2 q1 = lds2(rowp + 2);
                    float2 q2 = lds2(rowp + 4);
                    float2 q3 = lds2(rowp + 6);
                    float2 q4 = lds2(rowp + 8);
                    float2 p1[4] = {make_float2(q0.y, q1.x),
                                    make_float2(q1.y, q2.x),
                                    make_float2(q2.y, q3.x),
                                    make_float2(q3.y, q4.x)};
                    float2 p0[4] = {q0, q1, q2, q3};
                    float2 p2[4] = {q1, q2, q3, q4};
                    const float2* wrow = &s_w[(wrp * EE) * (CC * KK) + c * KK + ky * 3];
#pragma unroll
                    for (int ee = 0; ee < EE; ++ee) {
                        float2 w0 = wrow[ee * CC * KK + 0];
                        float2 w1 = wrow[ee * CC * KK + 1];
                        float2 w2 = wrow[ee * CC * KK + 2];
#pragma unroll
                        for (int j = 0; j < 4; ++j) {
                            acc[ee][j] = fma2(w0, p0[j], acc[ee][j]);
                            acc[ee][j] = fma2(w1, p1[j], acc[ee][j]);
                            acc[ee][j] = fma2(w2, p2[j], acc[ee][j]);
                        }
                    }
                }
            }
        } else {  // KS == 1
            for (int c = 0; c < CC; ++c) {
                const float* rowp = &s_in[(c * IN_ROWS + rr) * IN_COLS + x0];
                float2 p[4] = {lds2(rowp + 0), lds2(rowp + 2),
                               lds2(rowp + 4), lds2(rowp + 6)};
                const float2* wp = &s_w[(wrp * EE) * CC + c];
#pragma unroll
                for (int ee = 0; ee < EE; ++ee) {
                    float2 w = wp[ee * CC];
#pragma unroll
                    for (int j = 0; j < 4; ++j)
                        acc[ee][j] = fma2(w, p[j], acc[ee][j]);
                }
            }
        }
    }

    // ---- epilogue: + bias (folded BN), optional + residual, store ----
#pragma unroll
    for (int ee = 0; ee < EE; ++ee) {
        int e = eo + wrp * EE + ee;
        float b = bias[e];
        size_t obase = ((size_t)n * E_DIM + e) * HW_DIM + (size_t)(r0 + rr) * W_DIM + x0;
#pragma unroll
        for (int j = 0; j < 4; ++j) {
            float lo = acc[ee][j].x + b;
            float hi = acc[ee][j].y + b;
            if (ADD) {
                lo += addend[obase + 2 * j];
                hi += addend[obase + 2 * j + 1];
            }
            out[obase + 2 * j]     = lo;
            out[obase + 2 * j + 1] = hi;
        }
    }
}

// ---------------- launch ----------------
extern "C" void kernel_launch(void* const* d_in, const int* in_sizes, int n_in,
                              void* d_out, int out_size) {
    const float* x  = (const float*)d_in[0];
    const float* w3 = (const float*)d_in[1];
    const float* g3 = (const float*)d_in[2];
    const float* b3 = (const float*)d_in[3];
    const float* m3 = (const float*)d_in[4];
    const float* v3 = (const float*)d_in[5];
    const float* w4 = (const float*)d_in[6];
    const float* g4 = (const float*)d_in[7];
    const float* b4 = (const float*)d_in[8];
    const float* m4 = (const float*)d_in[9];
    const float* v4 = (const float*)d_in[10];
    const float* wr = (const float*)d_in[11];
    const float* gr = (const float*)d_in[12];
    const float* br = (const float*)d_in[13];
    const float* mr = (const float*)d_in[14];
    const float* vr = (const float*)d_in[15];
    float* out = (float*)d_out;

    float *spk, *mem, *w3f, *w4f, *wrf, *bias;
    cudaGetSymbolAddress((void**)&spk,  g_spk);
    cudaGetSymbolAddress((void**)&mem,  g_mem);
    cudaGetSymbolAddress((void**)&w3f,  g_w3f);
    cudaGetSymbolAddress((void**)&w4f,  g_w4f);
    cudaGetSymbolAddress((void**)&wrf,  g_wrf);
    cudaGetSymbolAddress((void**)&bias, g_bias);

    // launch 1-2: fold BN into weights/bias
    fold_all_w<<<(W3_N + W4_N + WR_N + 255) / 256, 256>>>(w3, g3, v3, w4, g4, v4, wr, gr, vr,
                                                          w3f, w4f, wrf);
    fold_all_b<<<3, E_DIM>>>(g3, b3, m3, v3, g4, b4, m4, v4, gr, br, mr, vr, bias);

    const int npt_c4 = B_DIM * C_DIM * HW_DIM / 4;
    const int npt_e4 = B_DIM * E_DIM * HW_DIM / 4;
    dim3 cgrid(H_DIM / 8, E_DIM / 32, TB_DIM);  // (4, 8, 64)

    // launch 3: LIF on raw input -> spikes (C=128)
    lif_kernel<<<(npt_c4 + 255) / 256, 256>>>((const float4*)x, (float4*)spk, npt_c4);
    // launch 4: conv3 (128->256) + BN
    conv_kernel<C_DIM, 3, 8, false><<<cgrid, 256>>>(spk, w3f, bias, nullptr, mem);
    // launch 5: LIF -> spikes (E=256)
    lif_kernel<<<(npt_e4 + 255) / 256, 256>>>((const float4*)mem, (float4*)spk, npt_e4);
    // launch 6 (profiled by ncu -s 5): conv4 (256->256) + BN
    conv_kernel<E_DIM, 3, 8, false><<<cgrid, 256>>>(spk, w4f, bias + E_DIM, nullptr, mem);
    // launch 7: LIF -> spikes
    lif_kernel<<<(npt_e4 + 255) / 256, 256>>>((const float4*)mem, (float4*)spk, npt_e4);
    // launch 8: residual 1x1 conv on ORIGINAL x + BN + spikes -> d_out
    conv_kernel<C_DIM, 1, 16, true><<<cgrid, 256>>>(x, wrf, bias + 2 * E_DIM, spk, out);
}

// round 10
// speedup vs baseline: 1.0763x; 1.0763x over previous
#include <cuda_runtime.h>

// ---------------- problem constants ----------------
#define T_DIM 4
#define B_DIM 16
#define C_DIM 128
#define E_DIM 256
#define H_DIM 32
#define W_DIM 32
#define HW_DIM (H_DIM * W_DIM)
#define TB_DIM (T_DIM * B_DIM)
#define BN_EPS 1e-5f
#define LIF_TAU 0.5f

// ---------------- device scratch (no allocations allowed) ----------------
__device__ float g_spk[(size_t)T_DIM * B_DIM * E_DIM * HW_DIM];  // spikes (67 MB)
__device__ float g_mem[(size_t)T_DIM * B_DIM * E_DIM * HW_DIM];  // pre-LIF (67 MB)
__device__ float g_w3f[E_DIM * C_DIM * 9];
__device__ float g_w4f[E_DIM * E_DIM * 9];
__device__ float g_wrf[E_DIM * C_DIM];
__device__ float g_bias[3 * E_DIM];   // [0]=conv3, [1]=conv4, [2]=residual

// ---------------- f32x2 packed-FMA helpers (sm_100+) ----------------
union F2U { float2 f2; unsigned long long u; };

__device__ __forceinline__ float2 fma2(float2 a, float2 b, float2 c) {
    F2U A, B, C, D;
    A.f2 = a; B.f2 = b; C.f2 = c;
    asm("fma.rn.f32x2 %0, %1, %2, %3;" : "=l"(D.u) : "l"(A.u), "l"(B.u), "l"(C.u));
    return D.f2;
}

__device__ __forceinline__ float2 lds2(const float* p) {
    return *reinterpret_cast<const float2*>(p);
}

// ---------------- BN folding (2 launches so conv4 lands at ncu slot 6) ----------------
#define W3_N (E_DIM * C_DIM * 9)
#define W4_N (E_DIM * E_DIM * 9)
#define WR_N (E_DIM * C_DIM)

__global__ void fold_all_w(const float* __restrict__ w3, const float* __restrict__ g3, const float* __restrict__ v3,
                           const float* __restrict__ w4, const float* __restrict__ g4, const float* __restrict__ v4,
                           const float* __restrict__ wr, const float* __restrict__ gr, const float* __restrict__ vr,
                           float* __restrict__ w3f, float* __restrict__ w4f, float* __restrict__ wrf) {
    int i = blockIdx.x * blockDim.x + threadIdx.x;
    if (i < W3_N) {
        int e = i / (C_DIM * 9);
        w3f[i] = w3[i] * (g3[e] * rsqrtf(v3[e] + BN_EPS));
    } else if (i < W3_N + W4_N) {
        int j = i - W3_N;
        int e = j / (E_DIM * 9);
        w4f[j] = w4[j] * (g4[e] * rsqrtf(v4[e] + BN_EPS));
    } else if (i < W3_N + W4_N + WR_N) {
        int j = i - W3_N - W4_N;
        int e = j / C_DIM;
        wrf[j] = wr[j] * (gr[e] * rsqrtf(vr[e] + BN_EPS));
    }
}

__global__ void fold_all_b(const float* __restrict__ g3, const float* __restrict__ b3,
                           const float* __restrict__ m3, const float* __restrict__ v3,
                           const float* __restrict__ g4, const float* __restrict__ b4,
                           const float* __restrict__ m4, const float* __restrict__ v4,
                           const float* __restrict__ gr, const float* __restrict__ br,
                           const float* __restrict__ mr, const float* __restrict__ vr,
                           float* __restrict__ bf) {
    int e = threadIdx.x;
    if (e >= E_DIM) return;
    if (blockIdx.x == 0)      bf[e]             = b3[e] - m3[e] * (g3[e] * rsqrtf(v3[e] + BN_EPS));
    else if (blockIdx.x == 1) bf[E_DIM + e]     = b4[e] - m4[e] * (g4[e] * rsqrtf(v4[e] + BN_EPS));
    else                      bf[2 * E_DIM + e] = br[e] - mr[e] * (gr[e] * rsqrtf(vr[e] + BN_EPS));
}

// ---------------- LIF: sequential over T, hard reset (float4, bit-identical math) ----------------
__global__ void lif_kernel(const float4* __restrict__ in,
                           float4* __restrict__ out, int npt4) {
    int i = blockIdx.x * blockDim.x + threadIdx.x;
    if (i >= npt4) return;
    float m0 = 0.f, m1 = 0.f, m2 = 0.f, m3 = 0.f;
#pragma unroll
    for (int t = 0; t < T_DIM; ++t) {
        float4 v = in[(size_t)t * npt4 + i];
        m0 = m0 * LIF_TAU + v.x;
        m1 = m1 * LIF_TAU + v.y;
        m2 = m2 * LIF_TAU + v.z;
        m3 = m3 * LIF_TAU + v.w;
        float4 s;
        s.x = (m0 >= 1.0f) ? 1.0f : 0.0f;  if (m0 >= 1.0f) m0 = 0.0f;
        s.y = (m1 >= 1.0f) ? 1.0f : 0.0f;  if (m1 >= 1.0f) m1 = 0.0f;
        s.z = (m2 >= 1.0f) ? 1.0f : 0.0f;  if (m2 >= 1.0f) m2 = 0.0f;
        s.w = (m3 >= 1.0f) ? 1.0f : 0.0f;  if (m3 >= 1.0f) m3 = 0.0f;
        out[(size_t)t * npt4 + i] = s;
    }
}

// ---------------- direct conv (+folded BN, optional residual add) ----------------
// ROUND-1 EXACT MATH: per-output FMA chain is (c ascending, ky, kx) lexicographic,
// fma.rn.f32x2, bias added once at the end, then optional addend. This chain order
// matches the reference's fp32 conv accumulation closely enough that spike flips
// stay at ~4 (measured rel_err 5.784606e-4 across three identical runs).
// Block: one image n, 64 output channels, 8 rows x 32 cols. 256 threads.
// Thread: 8 out-channels x 8 pixels (4 f32x2 pairs).
template <int CIN, int KS, int CC>
__global__ void __launch_bounds__(256, 2)
conv_kernel(const float* __restrict__ in,
            const float* __restrict__ wf,
            const float* __restrict__ bias,
            const float* __restrict__ addend,   // optional (residual fuse)
            float* __restrict__ out) {
    constexpr int ROWS    = 8;
    constexpr int IN_ROWS = ROWS + KS - 1;
    constexpr int IN_COLS = 34;
    constexpr int KK      = KS * KS;
    constexpr int IN_ELEMS = CC * IN_ROWS * IN_COLS;
    constexpr int W_ELEMS  = 64 * CC * KK;

    __shared__ __align__(16) float  s_in[IN_ELEMS];
    __shared__ __align__(16) float2 s_w[W_ELEMS];   // weights pre-duplicated {w, w}

    const int n  = blockIdx.z;
    const int eo = blockIdx.y * 64;
    const int r0 = blockIdx.x * ROWS;

    const int tid = threadIdx.x;
    const int eg  = tid >> 5;          // warp id: 8 e-values per warp (broadcast weights)
    const int pg  = tid & 31;
    const int rr  = pg >> 2;           // row within tile: 0..7
    const int x0  = (pg & 3) << 3;     // col base: 0,8,16,24

    float2 acc[8][4];
#pragma unroll
    for (int i = 0; i < 8; ++i)
#pragma unroll
        for (int j = 0; j < 4; ++j) acc[i][j] = make_float2(0.0f, 0.0f);

    for (int c0 = 0; c0 < CIN; c0 += CC) {
        __syncthreads();
        // ---- stage input tile (with halo + zero pad for KS==3) ----
        const float* inb = in + ((size_t)n * CIN + c0) * HW_DIM;
        for (int idx = tid; idx < IN_ELEMS; idx += 256) {
            int c   = idx / (IN_ROWS * IN_COLS);
            int rem = idx - c * (IN_ROWS * IN_COLS);
            int iy  = rem / IN_COLS;
            int ix  = rem - iy * IN_COLS;
            float val = 0.0f;
            if (KS == 3) {
                int gy = r0 + iy - 1;
                int gx = ix - 1;
                if ((unsigned)gy < (unsigned)H_DIM && (unsigned)gx < (unsigned)W_DIM)
                    val = inb[c * HW_DIM + gy * W_DIM + gx];
            } else {
                if (ix < W_DIM)
                    val = inb[c * HW_DIM + (r0 + iy) * W_DIM + ix];
            }
            s_in[idx] = val;
        }
        // ---- stage weights, duplicated into both f32x2 lanes ----
        for (int idx = tid; idx < W_ELEMS; idx += 256) {
            int e   = idx / (CC * KK);
            int rem = idx - e * (CC * KK);
            int c   = rem / KK;
            int k   = rem - c * KK;
            float wv = wf[((size_t)(eo + e) * CIN + (c0 + c)) * KK + k];
            s_w[idx] = make_float2(wv, wv);
        }
        __syncthreads();

        if (KS == 3) {
            for (int c = 0; c < CC; ++c) {
#pragma unroll
                for (int ky = 0; ky < 3; ++ky) {
                    const float* rowp = &s_in[(c * IN_ROWS + rr + ky) * IN_COLS + x0];
                    float2 q0 = lds2(rowp + 0);
                    float2 q1 = lds2(rowp + 2);
                    float2 q2 = lds2(rowp + 4);
                    float2 q3 = lds2(rowp + 6);
                    float2 q4 = lds2(rowp + 8);
                    float2 p0[4] = {q0, q1, q2, q3};                     // kx = 0
                    float2 p1[4] = {make_float2(q0.y, q1.x),             // kx = 1
                                    make_float2(q1.y, q2.x),
                                    make_float2(q2.y, q3.x),
                                    make_float2(q3.y, q4.x)};
                    float2 p2[4] = {q1, q2, q3, q4};                     // kx = 2
                    const float2* wrow = &s_w[(eg * 8) * (CC * KK) + c * KK + ky * 3];
#pragma unroll
                    for (int ee = 0; ee < 8; ++ee) {
                        float2 w0 = wrow[ee * CC * KK + 0];
                        float2 w1 = wrow[ee * CC * KK + 1];
                        float2 w2 = wrow[ee * CC * KK + 2];
#pragma unroll
                        for (int j = 0; j < 4; ++j) {
                            acc[ee][j] = fma2(w0, p0[j], acc[ee][j]);
                            acc[ee][j] = fma2(w1, p1[j], acc[ee][j]);
                            acc[ee][j] = fma2(w2, p2[j], acc[ee][j]);
                        }
                    }
                }
            }
        } else {  // KS == 1
            for (int c = 0; c < CC; ++c) {
                const float* rowp = &s_in[(c * IN_ROWS + rr) * IN_COLS + x0];
                float2 p[4] = {lds2(rowp + 0), lds2(rowp + 2),
                               lds2(rowp + 4), lds2(rowp + 6)};
                const float2* wp = &s_w[(eg * 8) * CC + c];
#pragma unroll
                for (int ee = 0; ee < 8; ++ee) {
                    float2 w = wp[ee * CC];
#pragma unroll
                    for (int j = 0; j < 4; ++j)
                        acc[ee][j] = fma2(w, p[j], acc[ee][j]);
                }
            }
        }
    }

    // ---- epilogue: + bias (folded BN), optional + residual, store ----
#pragma unroll
    for (int ee = 0; ee < 8; ++ee) {
        int e = eo + eg * 8 + ee;
        float b = bias[e];
        size_t obase = ((size_t)n * E_DIM + e) * HW_DIM + (size_t)(r0 + rr) * W_DIM + x0;
#pragma unroll
        for (int j = 0; j < 4; ++j) {
            float lo = acc[ee][j].x + b;
            float hi = acc[ee][j].y + b;
            if (addend) {
                lo += addend[obase + 2 * j];
                hi += addend[obase + 2 * j + 1];
            }
            out[obase + 2 * j]     = lo;
            out[obase + 2 * j + 1] = hi;
        }
    }
}

// ---------------- launch ----------------
extern "C" void kernel_launch(void* const* d_in, const int* in_sizes, int n_in,
                              void* d_out, int out_size) {
    const float* x  = (const float*)d_in[0];
    const float* w3 = (const float*)d_in[1];
    const float* g3 = (const float*)d_in[2];
    const float* b3 = (const float*)d_in[3];
    const float* m3 = (const float*)d_in[4];
    const float* v3 = (const float*)d_in[5];
    const float* w4 = (const float*)d_in[6];
    const float* g4 = (const float*)d_in[7];
    const float* b4 = (const float*)d_in[8];
    const float* m4 = (const float*)d_in[9];
    const float* v4 = (const float*)d_in[10];
    const float* wr = (const float*)d_in[11];
    const float* gr = (const float*)d_in[12];
    const float* br = (const float*)d_in[13];
    const float* mr = (const float*)d_in[14];
    const float* vr = (const float*)d_in[15];
    float* out = (float*)d_out;

    float *spk, *mem, *w3f, *w4f, *wrf, *bias;
    cudaGetSymbolAddress((void**)&spk,  g_spk);
    cudaGetSymbolAddress((void**)&mem,  g_mem);
    cudaGetSymbolAddress((void**)&w3f,  g_w3f);
    cudaGetSymbolAddress((void**)&w4f,  g_w4f);
    cudaGetSymbolAddress((void**)&wrf,  g_wrf);
    cudaGetSymbolAddress((void**)&bias, g_bias);

    const int npt_c4 = B_DIM * C_DIM * HW_DIM / 4;   // 524288
    const int npt_e4 = B_DIM * E_DIM * HW_DIM / 4;   // 1048576
    dim3 cgrid(H_DIM / 8, E_DIM / 64, TB_DIM);       // (4, 4, 64)

    // 1: fold BN into weights
    fold_all_w<<<(W3_N + W4_N + WR_N + 255) / 256, 256>>>(w3, g3, v3, w4, g4, v4, wr, gr, vr,
                                                          w3f, w4f, wrf);
    // 2: fold BN biases
    fold_all_b<<<3, E_DIM>>>(g3, b3, m3, v3, g4, b4, m4, v4, gr, br, mr, vr, bias);
    // 3: LIF on raw input -> spikes (C=128)
    lif_kernel<<<(npt_c4 + 255) / 256, 256>>>((const float4*)x, (float4*)spk, npt_c4);
    // 4: conv3 (128->256) + BN
    conv_kernel<C_DIM, 3, 8><<<cgrid, 256>>>(spk, w3f, bias, nullptr, mem);
    // 5: LIF -> spikes (E=256)
    lif_kernel<<<(npt_e4 + 255) / 256, 256>>>((const float4*)mem, (float4*)spk, npt_e4);
    // 6: conv4 (256->256) + BN   (ncu -s 5 profiles this launch)
    conv_kernel<E_DIM, 3, 8><<<cgrid, 256>>>(spk, w4f, bias + E_DIM, nullptr, mem);
    // 7: LIF -> spikes
    lif_kernel<<<(npt_e4 + 255) / 256, 256>>>((const float4*)mem, (float4*)spk, npt_e4);
    // 8: residual 1x1 conv on ORIGINAL x + BN + spikes -> d_out
    conv_kernel<C_DIM, 1, 16><<<cgrid, 256>>>(x, wrf, bias + 2 * E_DIM, spk, out);
}

// round 11
// speedup vs baseline: 1.0958x; 1.0181x over previous
#include <cuda_runtime.h>

// ---------------- problem constants ----------------
#define T_DIM 4
#define B_DIM 16
#define C_DIM 128
#define E_DIM 256
#define H_DIM 32
#define W_DIM 32
#define HW_DIM (H_DIM * W_DIM)
#define TB_DIM (T_DIM * B_DIM)
#define BN_EPS 1e-5f
#define LIF_TAU 0.5f

typedef unsigned long long u64;

// ---------------- device scratch (no allocations allowed) ----------------
__device__ float g_spk[(size_t)T_DIM * B_DIM * E_DIM * HW_DIM];  // spikes (67 MB)
__device__ float g_mem[(size_t)T_DIM * B_DIM * E_DIM * HW_DIM];  // pre-LIF (67 MB)
__device__ float g_w3f[E_DIM * C_DIM * 9];
__device__ float g_w4f[E_DIM * E_DIM * 9];
__device__ float g_wrf[E_DIM * C_DIM];
__device__ float g_bias[3 * E_DIM];   // [0]=conv3, [1]=conv4, [2]=residual

// ---------------- f32x2 packed-FMA helpers (sm_100+) ----------------
union F2U { float2 f2; u64 u; };

__device__ __forceinline__ u64 dup2(float w) {
    F2U u; u.f2 = make_float2(w, w); return u.u;
}
// in-place packed FMA: acc = a*b + acc  (no output-copy MOV)
__device__ __forceinline__ void fma2i(u64& acc, u64 a, u64 b) {
    asm("fma.rn.f32x2 %0, %1, %2, %0;" : "+l"(acc) : "l"(a), "l"(b));
}
__device__ __forceinline__ u64 ldsu64(const float* p) {
    return *reinterpret_cast<const u64*>(p);
}
// {a.hi, b.lo} -> packed pair for kx=1
__device__ __forceinline__ u64 shf64(u64 a, u64 b) {
    return (a >> 32) | (b << 32);
}

// ---------------- BN folding (2 launches so conv4 lands at ncu slot 6) ----------------
#define W3_N (E_DIM * C_DIM * 9)
#define W4_N (E_DIM * E_DIM * 9)
#define WR_N (E_DIM * C_DIM)

__global__ void fold_all_w(const float* __restrict__ w3, const float* __restrict__ g3, const float* __restrict__ v3,
                           const float* __restrict__ w4, const float* __restrict__ g4, const float* __restrict__ v4,
                           const float* __restrict__ wr, const float* __restrict__ gr, const float* __restrict__ vr,
                           float* __restrict__ w3f, float* __restrict__ w4f, float* __restrict__ wrf) {
    int i = blockIdx.x * blockDim.x + threadIdx.x;
    if (i < W3_N) {
        int e = i / (C_DIM * 9);
        w3f[i] = w3[i] * (g3[e] * rsqrtf(v3[e] + BN_EPS));
    } else if (i < W3_N + W4_N) {
        int j = i - W3_N;
        int e = j / (E_DIM * 9);
        w4f[j] = w4[j] * (g4[e] * rsqrtf(v4[e] + BN_EPS));
    } else if (i < W3_N + W4_N + WR_N) {
        int j = i - W3_N - W4_N;
        int e = j / C_DIM;
        wrf[j] = wr[j] * (gr[e] * rsqrtf(vr[e] + BN_EPS));
    }
}

__global__ void fold_all_b(const float* __restrict__ g3, const float* __restrict__ b3,
                           const float* __restrict__ m3, const float* __restrict__ v3,
                           const float* __restrict__ g4, const float* __restrict__ b4,
                           const float* __restrict__ m4, const float* __restrict__ v4,
                           const float* __restrict__ gr, const float* __restrict__ br,
                           const float* __restrict__ mr, const float* __restrict__ vr,
                           float* __restrict__ bf) {
    int e = threadIdx.x;
    if (e >= E_DIM) return;
    if (blockIdx.x == 0)      bf[e]             = b3[e] - m3[e] * (g3[e] * rsqrtf(v3[e] + BN_EPS));
    else if (blockIdx.x == 1) bf[E_DIM + e]     = b4[e] - m4[e] * (g4[e] * rsqrtf(v4[e] + BN_EPS));
    else                      bf[2 * E_DIM + e] = br[e] - mr[e] * (gr[e] * rsqrtf(vr[e] + BN_EPS));
}

// ---------------- LIF: sequential over T, hard reset (float4, bit-identical math) ----------------
__global__ void lif_kernel(const float4* __restrict__ in,
                           float4* __restrict__ out, int npt4) {
    int i = blockIdx.x * blockDim.x + threadIdx.x;
    if (i >= npt4) return;
    float m0 = 0.f, m1 = 0.f, m2 = 0.f, m3 = 0.f;
#pragma unroll
    for (int t = 0; t < T_DIM; ++t) {
        float4 v = in[(size_t)t * npt4 + i];
        m0 = m0 * LIF_TAU + v.x;
        m1 = m1 * LIF_TAU + v.y;
        m2 = m2 * LIF_TAU + v.z;
        m3 = m3 * LIF_TAU + v.w;
        float4 s;
        s.x = (m0 >= 1.0f) ? 1.0f : 0.0f;  if (m0 >= 1.0f) m0 = 0.0f;
        s.y = (m1 >= 1.0f) ? 1.0f : 0.0f;  if (m1 >= 1.0f) m1 = 0.0f;
        s.z = (m2 >= 1.0f) ? 1.0f : 0.0f;  if (m2 >= 1.0f) m2 = 0.0f;
        s.w = (m3 >= 1.0f) ? 1.0f : 0.0f;  if (m3 >= 1.0f) m3 = 0.0f;
        out[(size_t)t * npt4 + i] = s;
    }
}

// ---------------- direct conv (+folded BN, optional residual add) ----------------
// BIT-EXACT MATH vs the passing baseline: per-output FMA chain is (c ascending,
// ky, kx) lexicographic, fma.rn.f32x2, bias added once at the end, then addend.
// Operand mechanics only changed: in-place "+l" accumulators (no copy-back MOV),
// weights fetched as LDS.128 {w0,w1} + LDS.64 {w2}, pixels handled as u64.
// Block: one image n, 64 output channels, 8 rows x 32 cols. 256 threads.
// Thread: 8 out-channels x 8 pixels (4 f32x2 pairs).
template <int CIN, int KS, int CC>
__global__ void __launch_bounds__(256, 2)
conv_kernel(const float* __restrict__ in,
            const float* __restrict__ wf,
            const float* __restrict__ bias,
            const float* __restrict__ addend,   // optional (residual fuse)
            float* __restrict__ out) {
    constexpr int ROWS    = 8;
    constexpr int IN_ROWS = ROWS + KS - 1;
    constexpr int IN_COLS = 34;
    constexpr int IN_ELEMS = CC * IN_ROWS * IN_COLS;
    constexpr int W01_N = (KS == 3) ? 64 * CC * 3 : 1;   // {w_kx0, w_kx1} pairs
    constexpr int W2_N  = (KS == 3) ? 64 * CC * 3 : 64 * CC;

    __shared__ __align__(16) float      s_in[IN_ELEMS];
    __shared__ __align__(16) ulonglong2 s_w01[W01_N];
    __shared__ __align__(16) u64        s_w2[W2_N];

    const int n  = blockIdx.z;
    const int eo = blockIdx.y * 64;
    const int r0 = blockIdx.x * ROWS;

    const int tid = threadIdx.x;
    const int eg  = tid >> 5;          // warp id: 8 e-values per warp (broadcast weights)
    const int pg  = tid & 31;
    const int rr  = pg >> 2;           // row within tile: 0..7
    const int x0  = (pg & 3) << 3;     // col base: 0,8,16,24

    u64 acc[8][4];
#pragma unroll
    for (int i = 0; i < 8; ++i)
#pragma unroll
        for (int j = 0; j < 4; ++j) acc[i][j] = 0ull;   // bits of (0.f, 0.f)

    for (int c0 = 0; c0 < CIN; c0 += CC) {
        __syncthreads();
        // ---- stage input tile (with halo + zero pad for KS==3) ----
        const float* inb = in + ((size_t)n * CIN + c0) * HW_DIM;
        for (int idx = tid; idx < IN_ELEMS; idx += 256) {
            int c   = idx / (IN_ROWS * IN_COLS);
            int rem = idx - c * (IN_ROWS * IN_COLS);
            int iy  = rem / IN_COLS;
            int ix  = rem - iy * IN_COLS;
            float val = 0.0f;
            if (KS == 3) {
                int gy = r0 + iy - 1;
                int gx = ix - 1;
                if ((unsigned)gy < (unsigned)H_DIM && (unsigned)gx < (unsigned)W_DIM)
                    val = inb[c * HW_DIM + gy * W_DIM + gx];
            } else {
                if (ix < W_DIM)
                    val = inb[c * HW_DIM + (r0 + iy) * W_DIM + ix];
            }
            s_in[idx] = val;
        }
        // ---- stage weights (duplicated into both f32x2 lanes) ----
        if (KS == 3) {
            for (int idx = tid; idx < 64 * CC * 3; idx += 256) {
                int e   = idx / (CC * 3);
                int rem = idx - e * (CC * 3);
                int c   = rem / 3;
                int ky  = rem - c * 3;
                size_t base = ((size_t)(eo + e) * CIN + (c0 + c)) * 9 + ky * 3;
                float w0 = wf[base], w1 = wf[base + 1], w2 = wf[base + 2];
                s_w01[idx] = make_ulonglong2(dup2(w0), dup2(w1));
                s_w2[idx]  = dup2(w2);
            }
        } else {
            for (int idx = tid; idx < 64 * CC; idx += 256) {
                int e = idx / CC, c = idx - (idx / CC) * CC;
                s_w2[idx] = dup2(wf[(size_t)(eo + e) * CIN + (c0 + c)]);
            }
        }
        __syncthreads();

        if (KS == 3) {
            for (int c = 0; c < CC; ++c) {
#pragma unroll
                for (int ky = 0; ky < 3; ++ky) {
                    const float* rowp = &s_in[(c * IN_ROWS + rr + ky) * IN_COLS + x0];
                    u64 q0 = ldsu64(rowp + 0);
                    u64 q1 = ldsu64(rowp + 2);
                    u64 q2 = ldsu64(rowp + 4);
                    u64 q3 = ldsu64(rowp + 6);
                    u64 q4 = ldsu64(rowp + 8);
                    u64 p0[4] = {q0, q1, q2, q3};                        // kx = 0
                    u64 p1[4] = {shf64(q0, q1), shf64(q1, q2),           // kx = 1
                                 shf64(q2, q3), shf64(q3, q4)};
                    u64 p2[4] = {q1, q2, q3, q4};                        // kx = 2
                    const int wb = (eg * 8) * (CC * 3) + c * 3 + ky;
#pragma unroll
                    for (int ee = 0; ee < 8; ++ee) {
                        ulonglong2 w01 = s_w01[wb + ee * (CC * 3)];
                        u64        w2  = s_w2[wb + ee * (CC * 3)];
#pragma unroll
                        for (int j = 0; j < 4; ++j) {
                            fma2i(acc[ee][j], w01.x, p0[j]);
                            fma2i(acc[ee][j], w01.y, p1[j]);
                            fma2i(acc[ee][j], w2,    p2[j]);
                        }
                    }
                }
            }
        } else {  // KS == 1
            for (int c = 0; c < CC; ++c) {
                const float* rowp = &s_in[(c * IN_ROWS + rr) * IN_COLS + x0];
                u64 p[4] = {ldsu64(rowp + 0), ldsu64(rowp + 2),
                            ldsu64(rowp + 4), ldsu64(rowp + 6)};
                const int wb = (eg * 8) * CC + c;
#pragma unroll
                for (int ee = 0; ee < 8; ++ee) {
                    u64 w = s_w2[wb + ee * CC];
#pragma unroll
                    for (int j = 0; j < 4; ++j)
                        fma2i(acc[ee][j], w, p[j]);
                }
            }
        }
    }

    // ---- epilogue: + bias (folded BN), optional + residual, store ----
#pragma unroll
    for (int ee = 0; ee < 8; ++ee) {
        int e = eo + eg * 8 + ee;
        float b = bias[e];
        size_t obase = ((size_t)n * E_DIM + e) * HW_DIM + (size_t)(r0 + rr) * W_DIM + x0;
#pragma unroll
        for (int j = 0; j < 4; ++j) {
            F2U u; u.u = acc[ee][j];
            float lo = u.f2.x + b;
            float hi = u.f2.y + b;
            if (addend) {
                lo += addend[obase + 2 * j];
                hi += addend[obase + 2 * j + 1];
            }
            out[obase + 2 * j]     = lo;
            out[obase + 2 * j + 1] = hi;
        }
    }
}

// ---------------- launch ----------------
extern "C" void kernel_launch(void* const* d_in, const int* in_sizes, int n_in,
                              void* d_out, int out_size) {
    const float* x  = (const float*)d_in[0];
    const float* w3 = (const float*)d_in[1];
    const float* g3 = (const float*)d_in[2];
    const float* b3 = (const float*)d_in[3];
    const float* m3 = (const float*)d_in[4];
    const float* v3 = (const float*)d_in[5];
    const float* w4 = (const float*)d_in[6];
    const float* g4 = (const float*)d_in[7];
    const float* b4 = (const float*)d_in[8];
    const float* m4 = (const float*)d_in[9];
    const float* v4 = (const float*)d_in[10];
    const float* wr = (const float*)d_in[11];
    const float* gr = (const float*)d_in[12];
    const float* br = (const float*)d_in[13];
    const float* mr = (const float*)d_in[14];
    const float* vr = (const float*)d_in[15];
    float* out = (float*)d_out;

    float *spk, *mem, *w3f, *w4f, *wrf, *bias;
    cudaGetSymbolAddress((void**)&spk,  g_spk);
    cudaGetSymbolAddress((void**)&mem,  g_mem);
    cudaGetSymbolAddress((void**)&w3f,  g_w3f);
    cudaGetSymbolAddress((void**)&w4f,  g_w4f);
    cudaGetSymbolAddress((void**)&wrf,  g_wrf);
    cudaGetSymbolAddress((void**)&bias, g_bias);

    const int npt_c4 = B_DIM * C_DIM * HW_DIM / 4;   // 524288
    const int npt_e4 = B_DIM * E_DIM * HW_DIM / 4;   // 1048576
    dim3 cgrid(H_DIM / 8, E_DIM / 64, TB_DIM);       // (4, 4, 64)

    // 1: fold BN into weights
    fold_all_w<<<(W3_N + W4_N + WR_N + 255) / 256, 256>>>(w3, g3, v3, w4, g4, v4, wr, gr, vr,
                                                          w3f, w4f, wrf);
    // 2: fold BN biases
    fold_all_b<<<3, E_DIM>>>(g3, b3, m3, v3, g4, b4, m4, v4, gr, br, mr, vr, bias);
    // 3: LIF on raw input -> spikes (C=128)
    lif_kernel<<<(npt_c4 + 255) / 256, 256>>>((const float4*)x, (float4*)spk, npt_c4);
    // 4: conv3 (128->256) + BN
    conv_kernel<C_DIM, 3, 8><<<cgrid, 256>>>(spk, w3f, bias, nullptr, mem);
    // 5: LIF -> spikes (E=256)
    lif_kernel<<<(npt_e4 + 255) / 256, 256>>>((const float4*)mem, (float4*)spk, npt_e4);
    // 6: conv4 (256->256) + BN   (ncu -s 5 profiles this launch)
    conv_kernel<E_DIM, 3, 8><<<cgrid, 256>>>(spk, w4f, bias + E_DIM, nullptr, mem);
    // 7: LIF -> spikes
    lif_kernel<<<(npt_e4 + 255) / 256, 256>>>((const float4*)mem, (float4*)spk, npt_e4);
    // 8: residual 1x1 conv on ORIGINAL x + BN + spikes -> d_out
    conv_kernel<C_DIM, 1, 16><<<cgrid, 256>>>(x, wrf, bias + 2 * E_DIM, spk, out);
}

// round 12
// speedup vs baseline: 1.3267x; 1.2108x over previous
#include <cuda_runtime.h>
#include <cstdint>
#include <cstddef>

// ---------------- problem constants ----------------
#define T_DIM 4
#define B_DIM 16
#define C_DIM 128
#define E_DIM 256
#define H_DIM 32
#define W_DIM 32
#define HW_DIM (H_DIM * W_DIM)
#define TB_DIM (T_DIM * B_DIM)
#define BN_EPS 1e-5f
#define LIF_TAU 0.5f

typedef unsigned long long u64;

// ---------------- device scratch (no allocations allowed) ----------------
__device__ float g_spk[(size_t)T_DIM * B_DIM * E_DIM * HW_DIM];  // spikes (67 MB)
__device__ float g_mem[(size_t)T_DIM * B_DIM * E_DIM * HW_DIM];  // pre-LIF (67 MB)
// pre-packed duplicated weights, block-contiguous in the smem staging layout
#define P3_N (E_DIM * C_DIM * 3)     // (e,c,ky) triples conv3 = 98304
#define P4_N (E_DIM * E_DIM * 3)     // 196608
#define PR_N (E_DIM * C_DIM)         // (e,c) pairs residual = 32768
__device__ ulonglong2 g_w01p3[P3_N];
__device__ u64        g_w2p3[P3_N];
__device__ ulonglong2 g_w01p4[P4_N];
__device__ u64        g_w2p4[P4_N];
__device__ u64        g_wrp[PR_N];
__device__ float      g_bias[3 * E_DIM];   // [0]=conv3, [1]=conv4, [2]=residual

// ---------------- helpers ----------------
union F2U { float2 f2; u64 u; };

__device__ __forceinline__ u64 dup2(float w) {
    F2U u; u.f2 = make_float2(w, w); return u.u;
}
// in-place packed FMA: acc = a*b + acc
__device__ __forceinline__ void fma2i(u64& acc, u64 a, u64 b) {
    asm("fma.rn.f32x2 %0, %1, %2, %0;" : "+l"(acc) : "l"(a), "l"(b));
}
__device__ __forceinline__ u64 ldsu64(const float* p) {
    return *reinterpret_cast<const u64*>(p);
}
__device__ __forceinline__ uint32_t smem_u32(const void* p) {
    uint32_t a;
    asm("{ .reg .u64 t; cvta.to.shared.u64 t, %1; cvt.u32.u64 %0, t; }" : "=r"(a) : "l"(p));
    return a;
}
__device__ __forceinline__ void cp16(uint32_t saddr, const void* g) {
    asm volatile("cp.async.cg.shared.global [%0], [%1], 16;" :: "r"(saddr), "l"(g));
}
__device__ __forceinline__ void cp8(uint32_t saddr, const void* g) {
    asm volatile("cp.async.ca.shared.global [%0], [%1], 8;" :: "r"(saddr), "l"(g));
}
#define CP_COMMIT() asm volatile("cp.async.commit_group;" ::: "memory")
#define CP_WAIT0()  asm volatile("cp.async.wait_group 0;" ::: "memory")

// ---------------- fold BN + pack duplicated weights ----------------
// conv pack layout (KS=3): block (eb = e/64, cb = c/8), within block
//   idx = (e%64)*24 + (c%8)*3 + ky ; base = (eb*(CIN/8)+cb)*1536
// res pack layout (KS=1): block (eb, cb = c/16), idx = (e%64)*16 + (c%16);
//   base = (eb*(CIN/16)+cb)*1024
__global__ void fold_pack(const float* __restrict__ w3, const float* __restrict__ g3, const float* __restrict__ v3,
                          const float* __restrict__ w4, const float* __restrict__ g4, const float* __restrict__ v4,
                          const float* __restrict__ wr, const float* __restrict__ gr, const float* __restrict__ vr,
                          ulonglong2* __restrict__ w01p3, u64* __restrict__ w2p3,
                          ulonglong2* __restrict__ w01p4, u64* __restrict__ w2p4,
                          u64* __restrict__ wrp) {
    int i = blockIdx.x * blockDim.x + threadIdx.x;
    if (i < P3_N) {
        int e = i / (C_DIM * 3), r = i % (C_DIM * 3), c = r / 3, ky = r % 3;
        float s = g3[e] * rsqrtf(v3[e] + BN_EPS);
        size_t src = ((size_t)e * C_DIM + c) * 9 + ky * 3;
        float w0 = w3[src] * s, w1 = w3[src + 1] * s, w2 = w3[src + 2] * s;
        size_t pidx = ((size_t)(e >> 6) * (C_DIM / 8) + (c >> 3)) * 1536
                    + (e & 63) * 24 + (c & 7) * 3 + ky;
        w01p3[pidx] = make_ulonglong2(dup2(w0), dup2(w1));
        w2p3[pidx]  = dup2(w2);
    } else if (i < P3_N + P4_N) {
        int j = i - P3_N;
        int e = j / (E_DIM * 3), r = j % (E_DIM * 3), c = r / 3, ky = r % 3;
        float s = g4[e] * rsqrtf(v4[e] + BN_EPS);
        size_t src = ((size_t)e * E_DIM + c) * 9 + ky * 3;
        float w0 = w4[src] * s, w1 = w4[src + 1] * s, w2 = w4[src + 2] * s;
        size_t pidx = ((size_t)(e >> 6) * (E_DIM / 8) + (c >> 3)) * 1536
                    + (e & 63) * 24 + (c & 7) * 3 + ky;
        w01p4[pidx] = make_ulonglong2(dup2(w0), dup2(w1));
        w2p4[pidx]  = dup2(w2);
    } else if (i < P3_N + P4_N + PR_N) {
        int j = i - P3_N - P4_N;
        int e = j / C_DIM, c = j % C_DIM;
        float s = gr[e] * rsqrtf(vr[e] + BN_EPS);
        size_t pidx = ((size_t)(e >> 6) * (C_DIM / 16) + (c >> 4)) * 1024
                    + (e & 63) * 16 + (c & 15);
        wrp[pidx] = dup2(wr[(size_t)e * C_DIM + c] * s);
    }
}

__global__ void fold_b(const float* __restrict__ g3, const float* __restrict__ b3,
                       const float* __restrict__ m3, const float* __restrict__ v3,
                       const float* __restrict__ g4, const float* __restrict__ b4,
                       const float* __restrict__ m4, const float* __restrict__ v4,
                       const float* __restrict__ gr, const float* __restrict__ br,
                       const float* __restrict__ mr, const float* __restrict__ vr,
                       float* __restrict__ bf) {
    int e = threadIdx.x;
    if (e >= E_DIM) return;
    if (blockIdx.x == 0)      bf[e]             = b3[e] - m3[e] * (g3[e] * rsqrtf(v3[e] + BN_EPS));
    else if (blockIdx.x == 1) bf[E_DIM + e]     = b4[e] - m4[e] * (g4[e] * rsqrtf(v4[e] + BN_EPS));
    else                      bf[2 * E_DIM + e] = br[e] - mr[e] * (gr[e] * rsqrtf(vr[e] + BN_EPS));
}

// ---------------- LIF (float4, bit-identical math) ----------------
__global__ void lif_kernel(const float4* __restrict__ in,
                           float4* __restrict__ out, int npt4) {
    int i = blockIdx.x * blockDim.x + threadIdx.x;
    if (i >= npt4) return;
    float m0 = 0.f, m1 = 0.f, m2 = 0.f, m3 = 0.f;
#pragma unroll
    for (int t = 0; t < T_DIM; ++t) {
        float4 v = in[(size_t)t * npt4 + i];
        m0 = m0 * LIF_TAU + v.x;
        m1 = m1 * LIF_TAU + v.y;
        m2 = m2 * LIF_TAU + v.z;
        m3 = m3 * LIF_TAU + v.w;
        float4 s;
        s.x = (m0 >= 1.0f) ? 1.0f : 0.0f;  if (m0 >= 1.0f) m0 = 0.0f;
        s.y = (m1 >= 1.0f) ? 1.0f : 0.0f;  if (m1 >= 1.0f) m1 = 0.0f;
        s.z = (m2 >= 1.0f) ? 1.0f : 0.0f;  if (m2 >= 1.0f) m2 = 0.0f;
        s.w = (m3 >= 1.0f) ? 1.0f : 0.0f;  if (m3 >= 1.0f) m3 = 0.0f;
        out[(size_t)t * npt4 + i] = s;
    }
}

// ---------------- direct conv (+folded BN, optional residual add) ----------------
// BIT-EXACT chain: (c asc, ky, kx) lexicographic, fma.rn.f32x2, bias then addend.
// Mechanics: shifted smem copy for kx=1 operands (no shf64), cp.async pre-packed
// weights (no staging math), pointer-increment addressing.
template <int CIN, int KS, int CC>
__global__ void __launch_bounds__(256, 2)
conv_kernel(const float* __restrict__ in,
            const ulonglong2* __restrict__ w01p,   // packed (KS==3) else unused
            const u64* __restrict__ w2p,           // packed w2 (KS==3) / w (KS==1)
            const float* __restrict__ bias,
            const float* __restrict__ addend,
            float* __restrict__ out) {
    constexpr int ROWS    = 8;
    constexpr int IN_ROWS = ROWS + KS - 1;
    constexpr int IN_COLS = 34;
    constexpr int IN_ELEMS = CC * IN_ROWS * IN_COLS;
    constexpr int WN = (KS == 3) ? 64 * CC * 3 : 64 * CC;   // packed elems per block

    extern __shared__ __align__(16) char dsm[];
    float* s_in  = (float*)dsm;                                   // IN_ELEMS
    float* s_in1 = (KS == 3) ? s_in + IN_ELEMS : s_in;            // shifted copy (KS==3)
    char*  wbase = dsm + ((KS == 3) ? 2 : 1) * IN_ELEMS * 4;
    ulonglong2* s_w01 = (ulonglong2*)wbase;                       // KS==3 only
    u64* s_w2 = (KS == 3) ? (u64*)(wbase + WN * 16) : (u64*)wbase;

    const int n  = blockIdx.z;
    const int eo = blockIdx.y * 64;
    const int r0 = blockIdx.x * ROWS;

    const int tid = threadIdx.x;
    const int eg  = tid >> 5;
    const int pg  = tid & 31;
    const int rr  = pg >> 2;
    const int x0  = (pg & 3) << 3;

    const uint32_t sw01_a = smem_u32(s_w01);
    const uint32_t sw2_a  = smem_u32(s_w2);

    u64 acc[8][4];
#pragma unroll
    for (int i = 0; i < 8; ++i)
#pragma unroll
        for (int j = 0; j < 4; ++j) acc[i][j] = 0ull;

    for (int c0 = 0; c0 < CIN; c0 += CC) {
        __syncthreads();
        // ---- weights: contiguous cp.async from pre-packed GMEM ----
        if (KS == 3) {
            const size_t base = ((size_t)(eo >> 6) * (CIN / 8) + (c0 >> 3)) * 1536;
#pragma unroll
            for (int j = 0; j < WN / 256; ++j) {
                int idx = tid + j * 256;
                cp16(sw01_a + idx * 16, w01p + base + idx);
                cp8(sw2_a + idx * 8, w2p + base + idx);
            }
        } else {
            const size_t base = ((size_t)(eo >> 6) * (CIN / 16) + (c0 >> 4)) * 1024;
#pragma unroll
            for (int j = 0; j < WN / 256; ++j) {
                int idx = tid + j * 256;
                cp8(sw2_a + idx * 8, w2p + base + idx);
            }
        }
        CP_COMMIT();
        // ---- input tile (halo + zero pad), plus shifted copy for KS==3 ----
        const float* inb = in + ((size_t)n * CIN + c0) * HW_DIM;
        for (int idx = tid; idx < IN_ELEMS; idx += 256) {
            int c   = idx / (IN_ROWS * IN_COLS);
            int rem = idx - c * (IN_ROWS * IN_COLS);
            int iy  = rem / IN_COLS;
            int ix  = rem - iy * IN_COLS;
            float val = 0.0f;
            if (KS == 3) {
                int gy = r0 + iy - 1;
                int gx = ix - 1;
                if ((unsigned)gy < (unsigned)H_DIM && (unsigned)gx < (unsigned)W_DIM)
                    val = inb[c * HW_DIM + gy * W_DIM + gx];
            } else {
                if (ix < W_DIM)
                    val = inb[c * HW_DIM + (r0 + iy) * W_DIM + ix];
            }
            s_in[idx] = val;
            if (KS == 3 && ix > 0) s_in1[idx - 1] = val;
        }
        CP_WAIT0();
        __syncthreads();

        if (KS == 3) {
            for (int c = 0; c < CC; ++c) {
                const float* rowp  = &s_in[(c * IN_ROWS + rr) * IN_COLS + x0];
                const float* row1p = &s_in1[(c * IN_ROWS + rr) * IN_COLS + x0];
#pragma unroll
                for (int ky = 0; ky < 3; ++ky) {
                    u64 q0 = ldsu64(rowp + 0);
                    u64 q1 = ldsu64(rowp + 2);
                    u64 q2 = ldsu64(rowp + 4);
                    u64 q3 = ldsu64(rowp + 6);
                    u64 q4 = ldsu64(rowp + 8);
                    u64 p1a = ldsu64(row1p + 0);
                    u64 p1b = ldsu64(row1p + 2);
                    u64 p1c = ldsu64(row1p + 4);
                    u64 p1d = ldsu64(row1p + 6);
                    u64 p0[4] = {q0, q1, q2, q3};
                    u64 p1[4] = {p1a, p1b, p1c, p1d};
                    u64 p2[4] = {q1, q2, q3, q4};
                    const int wb = (eg * 8) * (CC * 3) + c * 3 + ky;
#pragma unroll
                    for (int ee = 0; ee < 8; ++ee) {
                        ulonglong2 w01 = s_w01[wb + ee * (CC * 3)];
                        u64        w2  = s_w2[wb + ee * (CC * 3)];
#pragma unroll
                        for (int j = 0; j < 4; ++j) {
                            fma2i(acc[ee][j], w01.x, p0[j]);
                            fma2i(acc[ee][j], w01.y, p1[j]);
                            fma2i(acc[ee][j], w2,    p2[j]);
                        }
                    }
                    rowp  += IN_COLS;
                    row1p += IN_COLS;
                }
            }
        } else {  // KS == 1
            for (int c = 0; c < CC; ++c) {
                const float* rowp = &s_in[(c * ROWS + rr) * IN_COLS + x0];
                u64 p[4] = {ldsu64(rowp + 0), ldsu64(rowp + 2),
                            ldsu64(rowp + 4), ldsu64(rowp + 6)};
                const int wb = (eg * 8) * CC + c;
#pragma unroll
                for (int ee = 0; ee < 8; ++ee) {
                    u64 w = s_w2[wb + ee * CC];
#pragma unroll
                    for (int j = 0; j < 4; ++j)
                        fma2i(acc[ee][j], w, p[j]);
                }
            }
        }
    }

    // ---- epilogue: + bias, optional + residual, store ----
#pragma unroll
    for (int ee = 0; ee < 8; ++ee) {
        int e = eo + eg * 8 + ee;
        float b = bias[e];
        size_t obase = ((size_t)n * E_DIM + e) * HW_DIM + (size_t)(r0 + rr) * W_DIM + x0;
#pragma unroll
        for (int j = 0; j < 4; ++j) {
            F2U u; u.u = acc[ee][j];
            float lo = u.f2.x + b;
            float hi = u.f2.y + b;
            if (addend) {
                lo += addend[obase + 2 * j];
                hi += addend[obase + 2 * j + 1];
            }
            out[obase + 2 * j]     = lo;
            out[obase + 2 * j + 1] = hi;
        }
    }
}

// ---------------- launch ----------------
extern "C" void kernel_launch(void* const* d_in, const int* in_sizes, int n_in,
                              void* d_out, int out_size) {
    const float* x  = (const float*)d_in[0];
    const float* w3 = (const float*)d_in[1];
    const float* g3 = (const float*)d_in[2];
    const float* b3 = (const float*)d_in[3];
    const float* m3 = (const float*)d_in[4];
    const float* v3 = (const float*)d_in[5];
    const float* w4 = (const float*)d_in[6];
    const float* g4 = (const float*)d_in[7];
    const float* b4 = (const float*)d_in[8];
    const float* m4 = (const float*)d_in[9];
    const float* v4 = (const float*)d_in[10];
    const float* wr = (const float*)d_in[11];
    const float* gr = (const float*)d_in[12];
    const float* br = (const float*)d_in[13];
    const float* mr = (const float*)d_in[14];
    const float* vr = (const float*)d_in[15];
    float* out = (float*)d_out;

    float *spk, *mem, *bias;
    ulonglong2 *w01p3, *w01p4;
    u64 *w2p3, *w2p4, *wrp;
    cudaGetSymbolAddress((void**)&spk,   g_spk);
    cudaGetSymbolAddress((void**)&mem,   g_mem);
    cudaGetSymbolAddress((void**)&w01p3, g_w01p3);
    cudaGetSymbolAddress((void**)&w2p3,  g_w2p3);
    cudaGetSymbolAddress((void**)&w01p4, g_w01p4);
    cudaGetSymbolAddress((void**)&w2p4,  g_w2p4);
    cudaGetSymbolAddress((void**)&wrp,   g_wrp);
    cudaGetSymbolAddress((void**)&bias,  g_bias);

    // dynamic smem sizes
    const int smem3 = 2 * (8 * 10 * 34 * 4) + 1536 * 16 + 1536 * 8;   // 58624
    const int smem1 = (16 * 8 * 34 * 4) + 1024 * 8;                   // 25600
    cudaFuncSetAttribute((const void*)conv_kernel<C_DIM, 3, 8>,
                         cudaFuncAttributeMaxDynamicSharedMemorySize, smem3);
    cudaFuncSetAttribute((const void*)conv_kernel<E_DIM, 3, 8>,
                         cudaFuncAttributeMaxDynamicSharedMemorySize, smem3);
    cudaFuncSetAttribute((const void*)conv_kernel<C_DIM, 1, 16>,
                         cudaFuncAttributeMaxDynamicSharedMemorySize, smem1);

    const int npt_c4 = B_DIM * C_DIM * HW_DIM / 4;
    const int npt_e4 = B_DIM * E_DIM * HW_DIM / 4;
    dim3 cgrid(H_DIM / 8, E_DIM / 64, TB_DIM);       // (4, 4, 64)

    // 1: fold + pack weights
    fold_pack<<<(P3_N + P4_N + PR_N + 255) / 256, 256>>>(
        w3, g3, v3, w4, g4, v4, wr, gr, vr, w01p3, w2p3, w01p4, w2p4, wrp);
    // 2: fold biases
    fold_b<<<3, E_DIM>>>(g3, b3, m3, v3, g4, b4, m4, v4, gr, br, mr, vr, bias);
    // 3: LIF on raw input -> spikes (C=128)
    lif_kernel<<<(npt_c4 + 255) / 256, 256>>>((const float4*)x, (float4*)spk, npt_c4);
    // 4: conv3 (128->256) + BN
    conv_kernel<C_DIM, 3, 8><<<cgrid, 256, smem3>>>(spk, w01p3, w2p3, bias, nullptr, mem);
    // 5: LIF -> spikes (E=256)
    lif_kernel<<<(npt_e4 + 255) / 256, 256>>>((const float4*)mem, (float4*)spk, npt_e4);
    // 6: conv4 (256->256) + BN   (ncu -s 5 profiles this launch)
    conv_kernel<E_DIM, 3, 8><<<cgrid, 256, smem3>>>(spk, w01p4, w2p4, bias + E_DIM, nullptr, mem);
    // 7: LIF -> spikes
    lif_kernel<<<(npt_e4 + 255) / 256, 256>>>((const float4*)mem, (float4*)spk, npt_e4);
    // 8: residual 1x1 conv on ORIGINAL x + BN + spikes -> d_out
    conv_kernel<C_DIM, 1, 16><<<cgrid, 256, smem1>>>(x, nullptr, wrp, bias + 2 * E_DIM, spk, out);
}

// round 13
// speedup vs baseline: 1.3961x; 1.0523x over previous
#include <cuda_runtime.h>
#include <cstdint>
#include <cstddef>

// ---------------- problem constants ----------------
#define T_DIM 4
#define B_DIM 16
#define C_DIM 128
#define E_DIM 256
#define HW_DIM 1024
#define TB_DIM 64
#define BN_EPS 1e-5f
#define LIF_TAU 0.5f

typedef unsigned long long u64;

#define P3_N (E_DIM * C_DIM * 3)
#define P4_N (E_DIM * E_DIM * 3)
#define PR_N (E_DIM * C_DIM)

// ---------------- device scratch (no allocations allowed) ----------------
__device__ float g_mem[(size_t)TB_DIM * E_DIM * HW_DIM];   // conv out NCHW (67 MB)
__device__ float g_spk[(size_t)TB_DIM * E_DIM * HW_DIM];   // lif2 spikes NCHW (67 MB)
// padded conv inputs: [n][c][34 rows][36 cols], zero borders (zero-init, never written)
__device__ float g_padA3[(size_t)TB_DIM * C_DIM * 34 * 36];  // x at col x+1
__device__ float g_padB3[(size_t)TB_DIM * C_DIM * 34 * 36];  // x at col x
__device__ float g_padA4[(size_t)TB_DIM * E_DIM * 34 * 36];
__device__ float g_padB4[(size_t)TB_DIM * E_DIM * 34 * 36];
// pre-packed duplicated weights, block-contiguous per (eo, c-chunk) stage
__device__ ulonglong2 g_w01p3[P3_N];
__device__ u64        g_w2p3[P3_N];
__device__ ulonglong2 g_w01p4[P4_N];
__device__ u64        g_w2p4[P4_N];
__device__ u64        g_wrp[PR_N];
__device__ float      g_bias[3 * E_DIM];

// ---------------- helpers ----------------
union F2U { float2 f2; u64 u; };

__device__ __forceinline__ u64 dup2(float w) {
    F2U u; u.f2 = make_float2(w, w); return u.u;
}
__device__ __forceinline__ void fma2i(u64& acc, u64 a, u64 b) {
    asm("fma.rn.f32x2 %0, %1, %2, %0;" : "+l"(acc) : "l"(a), "l"(b));
}
__device__ __forceinline__ u64 ldsu64(const float* p) {
    return *reinterpret_cast<const u64*>(p);
}
__device__ __forceinline__ uint32_t smem_u32(const void* p) {
    uint32_t a;
    asm("{ .reg .u64 t; cvta.to.shared.u64 t, %1; cvt.u32.u64 %0, t; }" : "=r"(a) : "l"(p));
    return a;
}
__device__ __forceinline__ void cp16(uint32_t saddr, const void* g) {
    asm volatile("cp.async.cg.shared.global [%0], [%1], 16;" :: "r"(saddr), "l"(g));
}
__device__ __forceinline__ void cp8(uint32_t saddr, const void* g) {
    asm volatile("cp.async.ca.shared.global [%0], [%1], 8;" :: "r"(saddr), "l"(g));
}
#define CP_COMMIT() asm volatile("cp.async.commit_group;" ::: "memory")
#define CP_WAIT0()  asm volatile("cp.async.wait_group 0;" ::: "memory")
#define CP_WAIT1()  asm volatile("cp.async.wait_group 1;" ::: "memory")

// ---------------- fold BN + pack duplicated weights ----------------
// conv pack (CC=4 stages): block (eb=e/64, cb=c/4) of 768:
//   idx = (e%64)*12 + (c%4)*3 + ky
// res pack (CC=16): block (eb, cb=c/16) of 1024: idx = (e%64)*16 + (c%16)
__global__ void fold_pack(const float* __restrict__ w3, const float* __restrict__ g3, const float* __restrict__ v3,
                          const float* __restrict__ w4, const float* __restrict__ g4, const float* __restrict__ v4,
                          const float* __restrict__ wr, const float* __restrict__ gr, const float* __restrict__ vr,
                          ulonglong2* __restrict__ w01p3, u64* __restrict__ w2p3,
                          ulonglong2* __restrict__ w01p4, u64* __restrict__ w2p4,
                          u64* __restrict__ wrp) {
    int i = blockIdx.x * blockDim.x + threadIdx.x;
    if (i < P3_N) {
        int e = i / (C_DIM * 3), r = i % (C_DIM * 3), c = r / 3, ky = r % 3;
        float s = g3[e] * rsqrtf(v3[e] + BN_EPS);
        size_t src = ((size_t)e * C_DIM + c) * 9 + ky * 3;
        float w0 = w3[src] * s, w1 = w3[src + 1] * s, w2 = w3[src + 2] * s;
        size_t pidx = ((size_t)(e >> 6) * (C_DIM / 4) + (c >> 2)) * 768
                    + (e & 63) * 12 + (c & 3) * 3 + ky;
        w01p3[pidx] = make_ulonglong2(dup2(w0), dup2(w1));
        w2p3[pidx]  = dup2(w2);
    } else if (i < P3_N + P4_N) {
        int j = i - P3_N;
        int e = j / (E_DIM * 3), r = j % (E_DIM * 3), c = r / 3, ky = r % 3;
        float s = g4[e] * rsqrtf(v4[e] + BN_EPS);
        size_t src = ((size_t)e * E_DIM + c) * 9 + ky * 3;
        float w0 = w4[src] * s, w1 = w4[src + 1] * s, w2 = w4[src + 2] * s;
        size_t pidx = ((size_t)(e >> 6) * (E_DIM / 4) + (c >> 2)) * 768
                    + (e & 63) * 12 + (c & 3) * 3 + ky;
        w01p4[pidx] = make_ulonglong2(dup2(w0), dup2(w1));
        w2p4[pidx]  = dup2(w2);
    } else if (i < P3_N + P4_N + PR_N) {
        int j = i - P3_N - P4_N;
        int e = j / C_DIM, c = j % C_DIM;
        float s = gr[e] * rsqrtf(vr[e] + BN_EPS);
        size_t pidx = ((size_t)(e >> 6) * (C_DIM / 16) + (c >> 4)) * 1024
                    + (e & 63) * 16 + (c & 15);
        wrp[pidx] = dup2(wr[(size_t)e * C_DIM + c] * s);
    }
}

__global__ void fold_b(const float* __restrict__ g3, const float* __restrict__ b3,
                       const float* __restrict__ m3, const float* __restrict__ v3,
                       const float* __restrict__ g4, const float* __restrict__ b4,
                       const float* __restrict__ m4, const float* __restrict__ v4,
                       const float* __restrict__ gr, const float* __restrict__ br,
                       const float* __restrict__ mr, const float* __restrict__ vr,
                       float* __restrict__ bf) {
    int e = threadIdx.x;
    if (e >= E_DIM) return;
    if (blockIdx.x == 0)      bf[e]             = b3[e] - m3[e] * (g3[e] * rsqrtf(v3[e] + BN_EPS));
    else if (blockIdx.x == 1) bf[E_DIM + e]     = b4[e] - m4[e] * (g4[e] * rsqrtf(v4[e] + BN_EPS));
    else                      bf[2 * E_DIM + e] = br[e] - mr[e] * (gr[e] * rsqrtf(vr[e] + BN_EPS));
}

// ---------------- LIF -> padded layouts A and B (bit-identical membrane math) ----------------
template <int CIN, int SH>   // SH = 8 + log2(CIN)
__global__ void lifP_kernel(const float4* __restrict__ in,
                            float* __restrict__ padA, float* __restrict__ padB) {
    int gid = blockIdx.x * blockDim.x + threadIdx.x;
    int xq = gid & 7;                 // x/4
    int y  = (gid >> 3) & 31;
    int c  = (gid >> 8) & (CIN - 1);
    int b  = gid >> SH;
    const int tstride = B_DIM * CIN * 256;       // float4 units per t
    const int base4 = (b * CIN + c) * 256 + y * 8 + xq;
    float m0 = 0.f, m1 = 0.f, m2 = 0.f, m3 = 0.f;
#pragma unroll
    for (int t = 0; t < T_DIM; ++t) {
        float4 v = in[t * tstride + base4];
        m0 = m0 * LIF_TAU + v.x;
        m1 = m1 * LIF_TAU + v.y;
        m2 = m2 * LIF_TAU + v.z;
        m3 = m3 * LIF_TAU + v.w;
        float4 s;
        s.x = (m0 >= 1.0f) ? 1.0f : 0.0f;  if (m0 >= 1.0f) m0 = 0.0f;
        s.y = (m1 >= 1.0f) ? 1.0f : 0.0f;  if (m1 >= 1.0f) m1 = 0.0f;
        s.z = (m2 >= 1.0f) ? 1.0f : 0.0f;  if (m2 >= 1.0f) m2 = 0.0f;
        s.w = (m3 >= 1.0f) ? 1.0f : 0.0f;  if (m3 >= 1.0f) m3 = 0.0f;
        int n = t * B_DIM + b;
        size_t rb = ((size_t)(n * CIN + c) * 34 + (y + 1)) * 36;
        *(float4*)(padB + rb + xq * 4) = s;           // layout B: x at col x
        padA[rb + xq * 4 + 1] = s.x;                  // layout A: x at col x+1
        padA[rb + xq * 4 + 2] = s.y;
        padA[rb + xq * 4 + 3] = s.z;
        padA[rb + xq * 4 + 4] = s.w;
    }
}

// ---------------- LIF -> NCHW fp32 spikes (for residual addend) ----------------
__global__ void lif_kernel(const float4* __restrict__ in,
                           float4* __restrict__ out, int npt4) {
    int i = blockIdx.x * blockDim.x + threadIdx.x;
    if (i >= npt4) return;
    float m0 = 0.f, m1 = 0.f, m2 = 0.f, m3 = 0.f;
#pragma unroll
    for (int t = 0; t < T_DIM; ++t) {
        float4 v = in[(size_t)t * npt4 + i];
        m0 = m0 * LIF_TAU + v.x;
        m1 = m1 * LIF_TAU + v.y;
        m2 = m2 * LIF_TAU + v.z;
        m3 = m3 * LIF_TAU + v.w;
        float4 s;
        s.x = (m0 >= 1.0f) ? 1.0f : 0.0f;  if (m0 >= 1.0f) m0 = 0.0f;
        s.y = (m1 >= 1.0f) ? 1.0f : 0.0f;  if (m1 >= 1.0f) m1 = 0.0f;
        s.z = (m2 >= 1.0f) ? 1.0f : 0.0f;  if (m2 >= 1.0f) m2 = 0.0f;
        s.w = (m3 >= 1.0f) ? 1.0f : 0.0f;  if (m3 >= 1.0f) m3 = 0.0f;
        out[(size_t)t * npt4 + i] = s;
    }
}

// ---------------- 3x3 conv: 3-deep cp.async ring, bit-exact FMA chain ----------------
template <int CIN>
__global__ void __launch_bounds__(256, 2)
conv3k(const float* __restrict__ padA, const float* __restrict__ padB,
       const ulonglong2* __restrict__ w01p, const u64* __restrict__ w2p,
       const float* __restrict__ bias, float* __restrict__ out) {
    constexpr int CC   = 4;
    constexpr int NST  = CIN / CC;
    constexpr int IN_F = CC * 10 * 36;              // 1440 floats per layout
    constexpr int IN_B = IN_F * 4;                  // 5760 B
    constexpr int WPC  = 64 * CC * 3;               // 768
    constexpr int W01_OFF = 2 * IN_B;               // 11520
    constexpr int W2_OFF  = W01_OFF + WPC * 16;     // 23808
    constexpr int SLOT    = W2_OFF + WPC * 8;       // 29952

    extern __shared__ __align__(16) char dsm[];
    const uint32_t sb = smem_u32(dsm);

    const int n  = blockIdx.z;
    const int eo = blockIdx.y * 64;
    const int r0 = blockIdx.x * 8;
    const int tid = threadIdx.x;
    const int eg  = tid >> 5;
    const int pg  = tid & 31;
    const int rr  = pg >> 2;
    const int x0  = (pg & 3) << 3;

    const float* baseA = padA + (((size_t)n * CIN) * 34 + r0) * 36;
    const float* baseB = padB + (((size_t)n * CIN) * 34 + r0) * 36;

    u64 acc[8][4];
#pragma unroll
    for (int i = 0; i < 8; ++i)
#pragma unroll
        for (int j = 0; j < 4; ++j) acc[i][j] = 0ull;

    auto load_stage = [&](int s) {
        if (s >= NST) return;
        const uint32_t slotb = sb + (s % 3) * SLOT;
        const int c0 = s * CC;
        // inputs: 2 layouts x 4ch x 10 rows x 9 cp16
        for (int k = tid; k < 720; k += 256) {
            int half = (k >= 360) ? 1 : 0;
            int k2 = k - half * 360;
            int cdiv = k2 / 90;
            int rem  = k2 - cdiv * 90;
            int rrow = rem / 9;
            int seg  = rem - rrow * 9;
            const float* src = (half ? baseB : baseA)
                             + (size_t)(c0 + cdiv) * (34 * 36) + rrow * 36 + seg * 4;
            cp16(slotb + half * IN_B + ((cdiv * 10 + rrow) * 36 + seg * 4) * 4, src);
        }
        // weights: contiguous packed block
        const size_t wb = ((size_t)(eo >> 6) * (CIN / 4) + s) * WPC;
        for (int k = tid; k < WPC; k += 256) {
            cp16(slotb + W01_OFF + k * 16, w01p + wb + k);
            cp8 (slotb + W2_OFF  + k * 8,  w2p  + wb + k);
        }
    };

    load_stage(0); CP_COMMIT();
    load_stage(1); CP_COMMIT();

    for (int s = 0; s < NST; ++s) {
        CP_WAIT1();            // group s complete (in-order)
        __syncthreads();       // visibility + ring-slot reuse safety
        load_stage(s + 2); CP_COMMIT();   // empty commit near end keeps counts uniform

        const char* slotc = dsm + (s % 3) * SLOT;
        const float* s_in  = (const float*)slotc;
        const float* s_in1 = (const float*)(slotc + IN_B);
        const ulonglong2* s_w01 = (const ulonglong2*)(slotc + W01_OFF);
        const u64* s_w2 = (const u64*)(slotc + W2_OFF);

#pragma unroll
        for (int c = 0; c < CC; ++c) {
            const float* rowp  = s_in  + (c * 10 + rr) * 36 + x0;
            const float* row1p = s_in1 + (c * 10 + rr) * 36 + x0;
#pragma unroll
            for (int ky = 0; ky < 3; ++ky) {
                u64 q0 = ldsu64(rowp + 0);
                u64 q1 = ldsu64(rowp + 2);
                u64 q2 = ldsu64(rowp + 4);
                u64 q3 = ldsu64(rowp + 6);
                u64 q4 = ldsu64(rowp + 8);
                u64 p1a = ldsu64(row1p + 0);
                u64 p1b = ldsu64(row1p + 2);
                u64 p1c = ldsu64(row1p + 4);
                u64 p1d = ldsu64(row1p + 6);
                u64 p0[4] = {q0, q1, q2, q3};
                u64 p1[4] = {p1a, p1b, p1c, p1d};
                u64 p2[4] = {q1, q2, q3, q4};
                const int wb2 = eg * 96 + c * 3 + ky;
#pragma unroll
                for (int ee = 0; ee < 8; ++ee) {
                    ulonglong2 w01 = s_w01[wb2 + ee * 12];
                    u64        w2  = s_w2[wb2 + ee * 12];
#pragma unroll
                    for (int j = 0; j < 4; ++j) {
                        fma2i(acc[ee][j], w01.x, p0[j]);
                        fma2i(acc[ee][j], w01.y, p1[j]);
                        fma2i(acc[ee][j], w2,    p2[j]);
                    }
                }
                rowp  += 36;
                row1p += 36;
            }
        }
    }

    // ---- epilogue: + bias, store (order unchanged) ----
#pragma unroll
    for (int ee = 0; ee < 8; ++ee) {
        int e = eo + eg * 8 + ee;
        float b = bias[e];
        size_t obase = ((size_t)n * E_DIM + e) * HW_DIM + (size_t)(r0 + rr) * 32 + x0;
#pragma unroll
        for (int j = 0; j < 4; ++j) {
            F2U u; u.u = acc[ee][j];
            out[obase + 2 * j]     = u.f2.x + b;
            out[obase + 2 * j + 1] = u.f2.y + b;
        }
    }
}

// ---------------- residual 1x1 conv: 2-ring cp.async + add spikes ----------------
__global__ void __launch_bounds__(256, 2)
res1k(const float* __restrict__ x, const u64* __restrict__ wrp,
      const float* __restrict__ bias, const float* __restrict__ addend,
      float* __restrict__ out) {
    constexpr int CC   = 16;
    constexpr int NST  = C_DIM / CC;                // 8
    constexpr int IN_F = CC * 8 * 36;               // 4608 floats
    constexpr int IN_B = IN_F * 4;                  // 18432 B
    constexpr int SLOT = IN_B + 1024 * 8;           // 26624 B

    extern __shared__ __align__(16) char dsm[];
    const uint32_t sb = smem_u32(dsm);

    const int n  = blockIdx.z;
    const int eo = blockIdx.y * 64;
    const int r0 = blockIdx.x * 8;
    const int tid = threadIdx.x;
    const int eg  = tid >> 5;
    const int pg  = tid & 31;
    const int rr  = pg >> 2;
    const int x0  = (pg & 3) << 3;

    const float* basex = x + ((size_t)n * C_DIM) * HW_DIM + r0 * 32;

    u64 acc[8][4];
#pragma unroll
    for (int i = 0; i < 8; ++i)
#pragma unroll
        for (int j = 0; j < 4; ++j) acc[i][j] = 0ull;

    auto load_stage = [&](int s) {
        if (s >= NST) return;
        const uint32_t slotb = sb + (s & 1) * SLOT;
        const int c0 = s * CC;
        for (int k = tid; k < 1024; k += 256) {
            int c = k >> 6;
            int rm = k & 63;
            int rrow = rm >> 3, seg = rm & 7;
            cp16(slotb + ((c * 8 + rrow) * 36 + seg * 4) * 4,
                 basex + (size_t)(c0 + c) * HW_DIM + rrow * 32 + seg * 4);
        }
        const size_t wb = ((size_t)(eo >> 6) * (C_DIM / 16) + s) * 1024;
        for (int k = tid; k < 1024; k += 256)
            cp8(slotb + IN_B + k * 8, wrp + wb + k);
    };

    load_stage(0); CP_COMMIT();

    for (int s = 0; s < NST; ++s) {
        CP_WAIT0();
        __syncthreads();
        load_stage(s + 1); CP_COMMIT();

        const char* slotc = dsm + (s & 1) * SLOT;
        const float* s_in = (const float*)slotc;
        const u64* s_w = (const u64*)(slotc + IN_B);
#pragma unroll 4
        for (int c = 0; c < CC; ++c) {
            const float* rowp = s_in + (c * 8 + rr) * 36 + x0;
            u64 p[4] = {ldsu64(rowp + 0), ldsu64(rowp + 2),
                        ldsu64(rowp + 4), ldsu64(rowp + 6)};
            const int wb2 = eg * 128 + c;
#pragma unroll
            for (int ee = 0; ee < 8; ++ee) {
                u64 w = s_w[wb2 + ee * 16];
#pragma unroll
                for (int j = 0; j < 4; ++j) fma2i(acc[ee][j], w, p[j]);
            }
        }
    }

    // ---- epilogue: + bias, + residual addend, store (order unchanged) ----
#pragma unroll
    for (int ee = 0; ee < 8; ++ee) {
        int e = eo + eg * 8 + ee;
        float b = bias[e];
        size_t obase = ((size_t)n * E_DIM + e) * HW_DIM + (size_t)(r0 + rr) * 32 + x0;
#pragma unroll
        for (int j = 0; j < 4; ++j) {
            F2U u; u.u = acc[ee][j];
            float lo = u.f2.x + b;
            float hi = u.f2.y + b;
            lo += addend[obase + 2 * j];
            hi += addend[obase + 2 * j + 1];
            out[obase + 2 * j]     = lo;
            out[obase + 2 * j + 1] = hi;
        }
    }
}

// ---------------- launch ----------------
extern "C" void kernel_launch(void* const* d_in, const int* in_sizes, int n_in,
                              void* d_out, int out_size) {
    const float* x  = (const float*)d_in[0];
    const float* w3 = (const float*)d_in[1];
    const float* g3 = (const float*)d_in[2];
    const float* b3 = (const float*)d_in[3];
    const float* m3 = (const float*)d_in[4];
    const float* v3 = (const float*)d_in[5];
    const float* w4 = (const float*)d_in[6];
    const float* g4 = (const float*)d_in[7];
    const float* b4 = (const float*)d_in[8];
    const float* m4 = (const float*)d_in[9];
    const float* v4 = (const float*)d_in[10];
    const float* wr = (const float*)d_in[11];
    const float* gr = (const float*)d_in[12];
    const float* br = (const float*)d_in[13];
    const float* mr = (const float*)d_in[14];
    const float* vr = (const float*)d_in[15];
    float* out = (float*)d_out;

    float *mem, *spk, *pA3, *pB3, *pA4, *pB4, *bias;
    ulonglong2 *w01p3, *w01p4;
    u64 *w2p3, *w2p4, *wrp;
    cudaGetSymbolAddress((void**)&mem,   g_mem);
    cudaGetSymbolAddress((void**)&spk,   g_spk);
    cudaGetSymbolAddress((void**)&pA3,   g_padA3);
    cudaGetSymbolAddress((void**)&pB3,   g_padB3);
    cudaGetSymbolAddress((void**)&pA4,   g_padA4);
    cudaGetSymbolAddress((void**)&pB4,   g_padB4);
    cudaGetSymbolAddress((void**)&w01p3, g_w01p3);
    cudaGetSymbolAddress((void**)&w2p3,  g_w2p3);
    cudaGetSymbolAddress((void**)&w01p4, g_w01p4);
    cudaGetSymbolAddress((void**)&w2p4,  g_w2p4);
    cudaGetSymbolAddress((void**)&wrp,   g_wrp);
    cudaGetSymbolAddress((void**)&bias,  g_bias);

    const int smem3 = 3 * 29952;   // 89856
    const int smemR = 2 * 26624;   // 53248
    cudaFuncSetAttribute((const void*)conv3k<C_DIM>,
                         cudaFuncAttributeMaxDynamicSharedMemorySize, smem3);
    cudaFuncSetAttribute((const void*)conv3k<E_DIM>,
                         cudaFuncAttributeMaxDynamicSharedMemorySize, smem3);
    cudaFuncSetAttribute((const void*)res1k,
                         cudaFuncAttributeMaxDynamicSharedMemorySize, smemR);

    dim3 cgrid(4, 4, 64);   // (rows/8, E/64, images)
    const int npt_e4 = B_DIM * E_DIM * HW_DIM / 4;

    // 1: fold + pack weights
    fold_pack<<<(P3_N + P4_N + PR_N + 255) / 256, 256>>>(
        w3, g3, v3, w4, g4, v4, wr, gr, vr, w01p3, w2p3, w01p4, w2p4, wrp);
    // 2: fold biases
    fold_b<<<3, E_DIM>>>(g3, b3, m3, v3, g4, b4, m4, v4, gr, br, mr, vr, bias);
    // 3: LIF0 -> padded spikes (C=128)
    lifP_kernel<C_DIM, 15><<<2048, 256>>>((const float4*)x, pA3, pB3);
    // 4: conv3 (128->256) + BN
    conv3k<C_DIM><<<cgrid, 256, smem3>>>(pA3, pB3, w01p3, w2p3, bias, mem);
    // 5: LIF1 -> padded spikes (E=256)
    lifP_kernel<E_DIM, 16><<<4096, 256>>>((const float4*)mem, pA4, pB4);
    // 6: conv4 (256->256) + BN   (ncu -s 5 profiles this launch)
    conv3k<E_DIM><<<cgrid, 256, smem3>>>(pA4, pB4, w01p4, w2p4, bias + E_DIM, mem);
    // 7: LIF2 -> NCHW spikes (residual addend)
    lif_kernel<<<(npt_e4 + 255) / 256, 256>>>((const float4*)mem, (float4*)spk, npt_e4);
    // 8: residual 1x1 + BN + add spikes -> d_out
    res1k<<<cgrid, 256, smemR>>>(x, wrp, bias + 2 * E_DIM, spk, out);
}

// round 14
// speedup vs baseline: 1.3980x; 1.0014x over previous
#include <cuda_runtime.h>
#include <cstdint>
#include <cstddef>

// ---------------- problem constants ----------------
#define T_DIM 4
#define B_DIM 16
#define C_DIM 128
#define E_DIM 256
#define HW_DIM 1024
#define TB_DIM 64
#define BN_EPS 1e-5f
#define LIF_TAU 0.5f

typedef unsigned long long u64;

#define P3_N (E_DIM * C_DIM * 3)
#define P4_N (E_DIM * E_DIM * 3)
#define PR_N (E_DIM * C_DIM)

// ---------------- device scratch (no allocations allowed) ----------------
__device__ float g_mem[(size_t)TB_DIM * E_DIM * HW_DIM];   // conv out NCHW (67 MB)
__device__ float g_spk[(size_t)TB_DIM * E_DIM * HW_DIM];   // lif2 spikes NCHW (67 MB)
// padded conv inputs: [n][c][34 rows][36 cols], zero borders (zero-init, never written)
__device__ float g_padA3[(size_t)TB_DIM * C_DIM * 34 * 36];  // x at col x+1
__device__ float g_padB3[(size_t)TB_DIM * C_DIM * 34 * 36];  // x at col x
__device__ float g_padA4[(size_t)TB_DIM * E_DIM * 34 * 36];
__device__ float g_padB4[(size_t)TB_DIM * E_DIM * 34 * 36];
// packed weights, e-contiguous per (c,ky) so w2 pairs load as LDS.128
__device__ ulonglong2 g_w01p3[P3_N];          // [blk][(c%4)*3+ky][e]  {w0dup,w1dup}
__device__ ulonglong2 g_w2p3[P3_N / 2];       // same order, e-pairs   {w2dup_e, w2dup_e+1}
__device__ ulonglong2 g_w01p4[P4_N];
__device__ ulonglong2 g_w2p4[P4_N / 2];
__device__ ulonglong2 g_wrp[PR_N / 2];        // [blk][(c%16)][e-pair]
__device__ float      g_bias[3 * E_DIM];

// ---------------- helpers ----------------
union F2U { float2 f2; u64 u; };

__device__ __forceinline__ u64 dup2(float w) {
    F2U u; u.f2 = make_float2(w, w); return u.u;
}
__device__ __forceinline__ void fma2i(u64& acc, u64 a, u64 b) {
    asm("fma.rn.f32x2 %0, %1, %2, %0;" : "+l"(acc) : "l"(a), "l"(b));
}
__device__ __forceinline__ u64 ldsu64(const float* p) {
    return *reinterpret_cast<const u64*>(p);
}
__device__ __forceinline__ ulonglong2 ldsu128(const float* p) {
    return *reinterpret_cast<const ulonglong2*>(p);
}
__device__ __forceinline__ uint32_t smem_u32(const void* p) {
    uint32_t a;
    asm("{ .reg .u64 t; cvta.to.shared.u64 t, %1; cvt.u32.u64 %0, t; }" : "=r"(a) : "l"(p));
    return a;
}
__device__ __forceinline__ void cp16(uint32_t saddr, const void* g) {
    asm volatile("cp.async.cg.shared.global [%0], [%1], 16;" :: "r"(saddr), "l"(g));
}
#define CP_COMMIT() asm volatile("cp.async.commit_group;" ::: "memory")
#define CP_WAIT0()  asm volatile("cp.async.wait_group 0;" ::: "memory")
#define CP_WAIT1()  asm volatile("cp.async.wait_group 1;" ::: "memory")

// ---------------- fold BN + pack weights ----------------
// conv (CC=4 stages): blk = (e/64)*(CIN/4) + c/4
//   w01 idx  (ulonglong2) = blk*768 + ((c%4)*3+ky)*64 + (e%64)
//   w2  idx  (u64 view)   = blk*768 + ((c%4)*3+ky)*64 + (e%64)
// res (CC=16): blk = (e/64)*(CIN/16) + c/16 ; u64 idx = blk*1024 + (c%16)*64 + (e%64)
__global__ void fold_pack(const float* __restrict__ w3, const float* __restrict__ g3, const float* __restrict__ v3,
                          const float* __restrict__ w4, const float* __restrict__ g4, const float* __restrict__ v4,
                          const float* __restrict__ wr, const float* __restrict__ gr, const float* __restrict__ vr,
                          ulonglong2* __restrict__ w01p3, ulonglong2* __restrict__ w2p3,
                          ulonglong2* __restrict__ w01p4, ulonglong2* __restrict__ w2p4,
                          ulonglong2* __restrict__ wrp) {
    int i = blockIdx.x * blockDim.x + threadIdx.x;
    if (i < P3_N) {
        int e = i / (C_DIM * 3), r = i % (C_DIM * 3), c = r / 3, ky = r % 3;
        float s = g3[e] * rsqrtf(v3[e] + BN_EPS);
        size_t src = ((size_t)e * C_DIM + c) * 9 + ky * 3;
        float w0 = w3[src] * s, w1 = w3[src + 1] * s, w2 = w3[src + 2] * s;
        size_t blk = (size_t)(e >> 6) * (C_DIM / 4) + (c >> 2);
        size_t idx = blk * 768 + ((c & 3) * 3 + ky) * 64 + (e & 63);
        w01p3[idx] = make_ulonglong2(dup2(w0), dup2(w1));
        ((u64*)w2p3)[idx] = dup2(w2);
    } else if (i < P3_N + P4_N) {
        int j = i - P3_N;
        int e = j / (E_DIM * 3), r = j % (E_DIM * 3), c = r / 3, ky = r % 3;
        float s = g4[e] * rsqrtf(v4[e] + BN_EPS);
        size_t src = ((size_t)e * E_DIM + c) * 9 + ky * 3;
        float w0 = w4[src] * s, w1 = w4[src + 1] * s, w2 = w4[src + 2] * s;
        size_t blk = (size_t)(e >> 6) * (E_DIM / 4) + (c >> 2);
        size_t idx = blk * 768 + ((c & 3) * 3 + ky) * 64 + (e & 63);
        w01p4[idx] = make_ulonglong2(dup2(w0), dup2(w1));
        ((u64*)w2p4)[idx] = dup2(w2);
    } else if (i < P3_N + P4_N + PR_N) {
        int j = i - P3_N - P4_N;
        int e = j / C_DIM, c = j % C_DIM;
        float s = gr[e] * rsqrtf(vr[e] + BN_EPS);
        size_t blk = (size_t)(e >> 6) * (C_DIM / 16) + (c >> 4);
        size_t idx = blk * 1024 + (c & 15) * 64 + (e & 63);
        ((u64*)wrp)[idx] = dup2(wr[(size_t)e * C_DIM + c] * s);
    }
}

__global__ void fold_b(const float* __restrict__ g3, const float* __restrict__ b3,
                       const float* __restrict__ m3, const float* __restrict__ v3,
                       const float* __restrict__ g4, const float* __restrict__ b4,
                       const float* __restrict__ m4, const float* __restrict__ v4,
                       const float* __restrict__ gr, const float* __restrict__ br,
                       const float* __restrict__ mr, const float* __restrict__ vr,
                       float* __restrict__ bf) {
    int e = threadIdx.x;
    if (e >= E_DIM) return;
    if (blockIdx.x == 0)      bf[e]             = b3[e] - m3[e] * (g3[e] * rsqrtf(v3[e] + BN_EPS));
    else if (blockIdx.x == 1) bf[E_DIM + e]     = b4[e] - m4[e] * (g4[e] * rsqrtf(v4[e] + BN_EPS));
    else                      bf[2 * E_DIM + e] = br[e] - mr[e] * (gr[e] * rsqrtf(vr[e] + BN_EPS));
}

// ---------------- LIF -> padded layouts A and B (bit-identical membrane math) ----------------
template <int CIN, int SH>   // SH = 8 + log2(CIN)
__global__ void lifP_kernel(const float4* __restrict__ in,
                            float* __restrict__ padA, float* __restrict__ padB) {
    int gid = blockIdx.x * blockDim.x + threadIdx.x;
    int xq = gid & 7;
    int y  = (gid >> 3) & 31;
    int c  = (gid >> 8) & (CIN - 1);
    int b  = gid >> SH;
    const int tstride = B_DIM * CIN * 256;
    const int base4 = (b * CIN + c) * 256 + y * 8 + xq;
    float m0 = 0.f, m1 = 0.f, m2 = 0.f, m3 = 0.f;
#pragma unroll
    for (int t = 0; t < T_DIM; ++t) {
        float4 v = in[t * tstride + base4];
        m0 = m0 * LIF_TAU + v.x;
        m1 = m1 * LIF_TAU + v.y;
        m2 = m2 * LIF_TAU + v.z;
        m3 = m3 * LIF_TAU + v.w;
        float4 s;
        s.x = (m0 >= 1.0f) ? 1.0f : 0.0f;  if (m0 >= 1.0f) m0 = 0.0f;
        s.y = (m1 >= 1.0f) ? 1.0f : 0.0f;  if (m1 >= 1.0f) m1 = 0.0f;
        s.z = (m2 >= 1.0f) ? 1.0f : 0.0f;  if (m2 >= 1.0f) m2 = 0.0f;
        s.w = (m3 >= 1.0f) ? 1.0f : 0.0f;  if (m3 >= 1.0f) m3 = 0.0f;
        int n = t * B_DIM + b;
        size_t rb = ((size_t)(n * CIN + c) * 34 + (y + 1)) * 36;
        *(float4*)(padB + rb + xq * 4) = s;
        padA[rb + xq * 4 + 1] = s.x;
        padA[rb + xq * 4 + 2] = s.y;
        padA[rb + xq * 4 + 3] = s.z;
        padA[rb + xq * 4 + 4] = s.w;
    }
}

// ---------------- LIF -> NCHW fp32 spikes (for residual addend) ----------------
__global__ void lif_kernel(const float4* __restrict__ in,
                           float4* __restrict__ out, int npt4) {
    int i = blockIdx.x * blockDim.x + threadIdx.x;
    if (i >= npt4) return;
    float m0 = 0.f, m1 = 0.f, m2 = 0.f, m3 = 0.f;
#pragma unroll
    for (int t = 0; t < T_DIM; ++t) {
        float4 v = in[(size_t)t * npt4 + i];
        m0 = m0 * LIF_TAU + v.x;
        m1 = m1 * LIF_TAU + v.y;
        m2 = m2 * LIF_TAU + v.z;
        m3 = m3 * LIF_TAU + v.w;
        float4 s;
        s.x = (m0 >= 1.0f) ? 1.0f : 0.0f;  if (m0 >= 1.0f) m0 = 0.0f;
        s.y = (m1 >= 1.0f) ? 1.0f : 0.0f;  if (m1 >= 1.0f) m1 = 0.0f;
        s.z = (m2 >= 1.0f) ? 1.0f : 0.0f;  if (m2 >= 1.0f) m2 = 0.0f;
        s.w = (m3 >= 1.0f) ? 1.0f : 0.0f;  if (m3 >= 1.0f) m3 = 0.0f;
        out[(size_t)t * npt4 + i] = s;
    }
}

// ---------------- 3x3 conv: 3-deep cp.async ring, vectorized LDS, bit-exact chain ----------------
template <int CIN>
__global__ void __launch_bounds__(256, 2)
conv3k(const float* __restrict__ padA, const float* __restrict__ padB,
       const ulonglong2* __restrict__ w01p, const ulonglong2* __restrict__ w2p,
       const float* __restrict__ bias, float* __restrict__ out) {
    constexpr int CC   = 4;
    constexpr int NST  = CIN / CC;
    constexpr int IN_F = CC * 10 * 36;              // 1440 floats per layout
    constexpr int IN_B = IN_F * 4;                  // 5760 B
    constexpr int W01_OFF = 2 * IN_B;               // 11520
    constexpr int W2_OFF  = W01_OFF + 768 * 16;     // 23808
    constexpr int SLOT    = W2_OFF + 384 * 16;      // 29952

    extern __shared__ __align__(16) char dsm[];
    const uint32_t sb = smem_u32(dsm);

    const int n  = blockIdx.z;
    const int eo = blockIdx.y * 64;
    const int r0 = blockIdx.x * 8;
    const int tid = threadIdx.x;
    const int eg  = tid >> 5;
    const int pg  = tid & 31;
    const int rr  = pg >> 2;
    const int x0  = (pg & 3) << 3;

    const float* baseA = padA + (((size_t)n * CIN) * 34 + r0) * 36;
    const float* baseB = padB + (((size_t)n * CIN) * 34 + r0) * 36;

    u64 acc[8][4];
#pragma unroll
    for (int i = 0; i < 8; ++i)
#pragma unroll
        for (int j = 0; j < 4; ++j) acc[i][j] = 0ull;

    auto load_stage = [&](int s) {
        if (s >= NST) return;
        const uint32_t slotb = sb + (s % 3) * SLOT;
        const int c0 = s * CC;
        // inputs: 2 layouts x 4ch x 10 rows x 9 cp16
        for (int k = tid; k < 720; k += 256) {
            int half = (k >= 360) ? 1 : 0;
            int k2 = k - half * 360;
            int cdiv = k2 / 90;
            int rem  = k2 - cdiv * 90;
            int rrow = rem / 9;
            int seg  = rem - rrow * 9;
            const float* src = (half ? baseB : baseA)
                             + (size_t)(c0 + cdiv) * (34 * 36) + rrow * 36 + seg * 4;
            cp16(slotb + half * IN_B + ((cdiv * 10 + rrow) * 36 + seg * 4) * 4, src);
        }
        // weights: contiguous packed blocks
        const size_t wb = ((size_t)(eo >> 6) * (CIN / 4) + s);
        const ulonglong2* w01src = w01p + wb * 768;
        const ulonglong2* w2src  = w2p  + wb * 384;
        for (int k = tid; k < 768; k += 256)
            cp16(slotb + W01_OFF + k * 16, w01src + k);
        for (int k = tid; k < 384; k += 256)
            cp16(slotb + W2_OFF + k * 16, w2src + k);
    };

    load_stage(0); CP_COMMIT();
    load_stage(1); CP_COMMIT();

    for (int s = 0; s < NST; ++s) {
        CP_WAIT1();
        __syncthreads();
        load_stage(s + 2); CP_COMMIT();

        const char* slotc = dsm + (s % 3) * SLOT;
        const float* s_in  = (const float*)slotc;
        const float* s_in1 = (const float*)(slotc + IN_B);
        const ulonglong2* s_w01 = (const ulonglong2*)(slotc + W01_OFF);
        const ulonglong2* s_w2  = (const ulonglong2*)(slotc + W2_OFF);

#pragma unroll
        for (int c = 0; c < CC; ++c) {
            const float* rowp  = s_in  + (c * 10 + rr) * 36 + x0;
            const float* row1p = s_in1 + (c * 10 + rr) * 36 + x0;
#pragma unroll
            for (int ky = 0; ky < 3; ++ky) {
                ulonglong2 q01 = ldsu128(rowp);          // q0,q1
                ulonglong2 q23 = ldsu128(rowp + 4);      // q2,q3
                u64 q4 = ldsu64(rowp + 8);
                ulonglong2 pA = ldsu128(row1p);          // p1a,p1b
                ulonglong2 pB = ldsu128(row1p + 4);      // p1c,p1d
                u64 p0[4] = {q01.x, q01.y, q23.x, q23.y};
                u64 p1[4] = {pA.x, pA.y, pB.x, pB.y};
                u64 p2[4] = {q01.y, q23.x, q23.y, q4};
                const ulonglong2* w01 = s_w01 + (c * 3 + ky) * 64 + eg * 8;
                const ulonglong2* w2v = s_w2  + (c * 3 + ky) * 32 + eg * 4;
#pragma unroll
                for (int eh = 0; eh < 4; ++eh) {
                    ulonglong2 w2pair = w2v[eh];
#pragma unroll
                    for (int sub = 0; sub < 2; ++sub) {
                        int ee = eh * 2 + sub;
                        ulonglong2 w01e = w01[ee];
                        u64 w2e = sub ? w2pair.y : w2pair.x;
#pragma unroll
                        for (int j = 0; j < 4; ++j) {
                            fma2i(acc[ee][j], w01e.x, p0[j]);
                            fma2i(acc[ee][j], w01e.y, p1[j]);
                            fma2i(acc[ee][j], w2e,    p2[j]);
                        }
                    }
                }
                rowp  += 36;
                row1p += 36;
            }
        }
    }

    // ---- epilogue: + bias, store (order unchanged) ----
#pragma unroll
    for (int ee = 0; ee < 8; ++ee) {
        int e = eo + eg * 8 + ee;
        float b = bias[e];
        size_t obase = ((size_t)n * E_DIM + e) * HW_DIM + (size_t)(r0 + rr) * 32 + x0;
#pragma unroll
        for (int j = 0; j < 4; ++j) {
            F2U u; u.u = acc[ee][j];
            out[obase + 2 * j]     = u.f2.x + b;
            out[obase + 2 * j + 1] = u.f2.y + b;
        }
    }
}

// ---------------- residual 1x1 conv: 2-ring cp.async + add spikes ----------------
__global__ void __launch_bounds__(256, 2)
res1k(const float* __restrict__ x, const ulonglong2* __restrict__ wrp,
      const float* __restrict__ bias, const float* __restrict__ addend,
      float* __restrict__ out) {
    constexpr int CC   = 16;
    constexpr int NST  = C_DIM / CC;                // 8
    constexpr int IN_F = CC * 8 * 36;               // 4608 floats
    constexpr int IN_B = IN_F * 4;                  // 18432 B
    constexpr int SLOT = IN_B + 512 * 16;           // 26624 B

    extern __shared__ __align__(16) char dsm[];
    const uint32_t sb = smem_u32(dsm);

    const int n  = blockIdx.z;
    const int eo = blockIdx.y * 64;
    const int r0 = blockIdx.x * 8;
    const int tid = threadIdx.x;
    const int eg  = tid >> 5;
    const int pg  = tid & 31;
    const int rr  = pg >> 2;
    const int x0  = (pg & 3) << 3;

    const float* basex = x + ((size_t)n * C_DIM) * HW_DIM + r0 * 32;

    u64 acc[8][4];
#pragma unroll
    for (int i = 0; i < 8; ++i)
#pragma unroll
        for (int j = 0; j < 4; ++j) acc[i][j] = 0ull;

    auto load_stage = [&](int s) {
        if (s >= NST) return;
        const uint32_t slotb = sb + (s & 1) * SLOT;
        const int c0 = s * CC;
        for (int k = tid; k < 1024; k += 256) {
            int c = k >> 6;
            int rm = k & 63;
            int rrow = rm >> 3, seg = rm & 7;
            cp16(slotb + ((c * 8 + rrow) * 36 + seg * 4) * 4,
                 basex + (size_t)(c0 + c) * HW_DIM + rrow * 32 + seg * 4);
        }
        const ulonglong2* wsrc = wrp + ((size_t)(eo >> 6) * (C_DIM / 16) + s) * 512;
        for (int k = tid; k < 512; k += 256)
            cp16(slotb + IN_B + k * 16, wsrc + k);
    };

    load_stage(0); CP_COMMIT();

    for (int s = 0; s < NST; ++s) {
        CP_WAIT0();
        __syncthreads();
        load_stage(s + 1); CP_COMMIT();

        const char* slotc = dsm + (s & 1) * SLOT;
        const float* s_in = (const float*)slotc;
        const ulonglong2* s_w = (const ulonglong2*)(slotc + IN_B);
#pragma unroll 4
        for (int c = 0; c < CC; ++c) {
            const float* rowp = s_in + (c * 8 + rr) * 36 + x0;
            ulonglong2 pa = ldsu128(rowp);
            ulonglong2 pb = ldsu128(rowp + 4);
            u64 p[4] = {pa.x, pa.y, pb.x, pb.y};
            const ulonglong2* wv = s_w + c * 32 + eg * 4;
#pragma unroll
            for (int eh = 0; eh < 4; ++eh) {
                ulonglong2 wp2 = wv[eh];
#pragma unroll
                for (int sub = 0; sub < 2; ++sub) {
                    int ee = eh * 2 + sub;
                    u64 w = sub ? wp2.y : wp2.x;
#pragma unroll
                    for (int j = 0; j < 4; ++j) fma2i(acc[ee][j], w, p[j]);
                }
            }
        }
    }

    // ---- epilogue: + bias, + residual addend, store (order unchanged) ----
#pragma unroll
    for (int ee = 0; ee < 8; ++ee) {
        int e = eo + eg * 8 + ee;
        float b = bias[e];
        size_t obase = ((size_t)n * E_DIM + e) * HW_DIM + (size_t)(r0 + rr) * 32 + x0;
#pragma unroll
        for (int j = 0; j < 4; ++j) {
            F2U u; u.u = acc[ee][j];
            float lo = u.f2.x + b;
            float hi = u.f2.y + b;
            lo += addend[obase + 2 * j];
            hi += addend[obase + 2 * j + 1];
            out[obase + 2 * j]     = lo;
            out[obase + 2 * j + 1] = hi;
        }
    }
}

// ---------------- launch ----------------
extern "C" void kernel_launch(void* const* d_in, const int* in_sizes, int n_in,
                              void* d_out, int out_size) {
    const float* x  = (const float*)d_in[0];
    const float* w3 = (const float*)d_in[1];
    const float* g3 = (const float*)d_in[2];
    const float* b3 = (const float*)d_in[3];
    const float* m3 = (const float*)d_in[4];
    const float* v3 = (const float*)d_in[5];
    const float* w4 = (const float*)d_in[6];
    const float* g4 = (const float*)d_in[7];
    const float* b4 = (const float*)d_in[8];
    const float* m4 = (const float*)d_in[9];
    const float* v4 = (const float*)d_in[10];
    const float* wr = (const float*)d_in[11];
    const float* gr = (const float*)d_in[12];
    const float* br = (const float*)d_in[13];
    const float* mr = (const float*)d_in[14];
    const float* vr = (const float*)d_in[15];
    float* out = (float*)d_out;

    float *mem, *spk, *pA3, *pB3, *pA4, *pB4, *bias;
    ulonglong2 *w01p3, *w01p4, *w2p3, *w2p4, *wrp;
    cudaGetSymbolAddress((void**)&mem,   g_mem);
    cudaGetSymbolAddress((void**)&spk,   g_spk);
    cudaGetSymbolAddress((void**)&pA3,   g_padA3);
    cudaGetSymbolAddress((void**)&pB3,   g_padB3);
    cudaGetSymbolAddress((void**)&pA4,   g_padA4);
    cudaGetSymbolAddress((void**)&pB4,   g_padB4);
    cudaGetSymbolAddress((void**)&w01p3, g_w01p3);
    cudaGetSymbolAddress((void**)&w2p3,  g_w2p3);
    cudaGetSymbolAddress((void**)&w01p4, g_w01p4);
    cudaGetSymbolAddress((void**)&w2p4,  g_w2p4);
    cudaGetSymbolAddress((void**)&wrp,   g_wrp);
    cudaGetSymbolAddress((void**)&bias,  g_bias);

    const int smem3 = 3 * 29952;   // 89856
    const int smemR = 2 * 26624;   // 53248
    cudaFuncSetAttribute((const void*)conv3k<C_DIM>,
                         cudaFuncAttributeMaxDynamicSharedMemorySize, smem3);
    cudaFuncSetAttribute((const void*)conv3k<E_DIM>,
                         cudaFuncAttributeMaxDynamicSharedMemorySize, smem3);
    cudaFuncSetAttribute((const void*)res1k,
                         cudaFuncAttributeMaxDynamicSharedMemorySize, smemR);

    dim3 cgrid(4, 4, 64);
    const int npt_e4 = B_DIM * E_DIM * HW_DIM / 4;

    // 1: fold + pack weights
    fold_pack<<<(P3_N + P4_N + PR_N + 255) / 256, 256>>>(
        w3, g3, v3, w4, g4, v4, wr, gr, vr, w01p3, w2p3, w01p4, w2p4, wrp);
    // 2: fold biases
    fold_b<<<3, E_DIM>>>(g3, b3, m3, v3, g4, b4, m4, v4, gr, br, mr, vr, bias);
    // 3: LIF0 -> padded spikes (C=128)
    lifP_kernel<C_DIM, 15><<<2048, 256>>>((const float4*)x, pA3, pB3);
    // 4: conv3 (128->256) + BN
    conv3k<C_DIM><<<cgrid, 256, smem3>>>(pA3, pB3, w01p3, w2p3, bias, mem);
    // 5: LIF1 -> padded spikes (E=256)
    lifP_kernel<E_DIM, 16><<<4096, 256>>>((const float4*)mem, pA4, pB4);
    // 6: conv4 (256->256) + BN   (ncu -s 5 profiles this launch)
    conv3k<E_DIM><<<cgrid, 256, smem3>>>(pA4, pB4, w01p4, w2p4, bias + E_DIM, mem);
    // 7: LIF2 -> NCHW spikes (residual addend)
    lif_kernel<<<(npt_e4 + 255) / 256, 256>>>((const float4*)mem, (float4*)spk, npt_e4);
    // 8: residual 1x1 + BN + add spikes -> d_out
    res1k<<<cgrid, 256, smemR>>>(x, wrp, bias + 2 * E_DIM, spk, out);
}